// round 4
// baseline (speedup 1.0000x reference)
#include <cuda_runtime.h>
#include <math.h>

#define NN 1024
#define KK 32
#define HH 256
#define DEn 128
#define NE 8
#define NHn 8
#define DHn 32
#define FF 512
#define SS 260   // 16B-aligned padded slot stride

typedef unsigned long long ull;

__device__ int   g_te[NN * 2];
__device__ float g_tg[NN * 2];

// prepacked weights: k-pairs (W[k][j], W[k+1][j]) in one ull, row-major over k-pairs
#define OFF_WE   0u
#define OFF_WN   131072u
#define OFF_WM   655360u
#define OFF_WQKV 1179648u
#define OFF_WO   1966080u
#define OFF_W1N  2228224u
#define OFF_W2N  2752512u
#define OFF_W1E  3276800u
#define OFF_W2E  3801088u
#define WP_TOTAL 4325376u
__device__ ull g_wp[WP_TOTAL];

__device__ __forceinline__ float gelu_f(float x) {
    float x3 = x * x * x;
    return 0.5f * x * (1.0f + tanhf(0.7978845608028654f * (x + 0.044715f * x3)));
}
__device__ __forceinline__ ull pk2(float lo, float hi) {
    ull r; asm("mov.b64 %0,{%1,%2};" : "=l"(r) : "f"(lo), "f"(hi)); return r;
}
__device__ __forceinline__ void upk2(ull v, float& lo, float& hi) {
    asm("mov.b64 {%0,%1},%2;" : "=f"(lo), "=f"(hi) : "l"(v));
}
__device__ __forceinline__ void fma2(ull& d, ull a, ull b) {
    asm("fma.rn.f32x2 %0,%1,%2,%0;" : "+l"(d) : "l"(a), "l"(b));
}
__device__ __forceinline__ float fold(ull v) {
    float lo, hi; upk2(v, lo, hi); return lo + hi;
}

__device__ __forceinline__ float block_sum512(float v, float* red) {
    #pragma unroll
    for (int o = 16; o; o >>= 1) v += __shfl_xor_sync(0xffffffffu, v, o);
    int tid = threadIdx.x;
    if ((tid & 31) == 0) red[tid >> 5] = v;
    __syncthreads();
    float s = 0.f;
    #pragma unroll
    for (int i = 0; i < 16; i++) s += red[i];
    __syncthreads();
    return s;
}

// ---- 8-row x 2-adjacent-col f32x2 GEMM with weight prefetch ----
// thread owns output cols (col2, col2+1); weights: one LDG.128 per k-pair
__device__ __forceinline__ void initacc8(ull acc[8][2], const float* bias, int col2) {
    float2 b = *(const float2*)(bias + col2);
    ull b0 = pk2(b.x, 0.f), b1 = pk2(b.y, 0.f);
    #pragma unroll
    for (int r = 0; r < 8; r++) { acc[r][0] = b0; acc[r][1] = b1; }
}

__device__ __forceinline__ void gemm8x2(ull acc[8][2],
    const float* __restrict__ sIn, int inS, int hin,
    const ull* __restrict__ Wp, int wld, int col2, int rbase)
{
    const float* ip = sIn + rbase * inS;
    const ull* w = Wp + col2;
    ulonglong2 w0 = *(const ulonglong2*)(w);          // k-pair 0: cols col2,col2+1
    ulonglong2 w1 = *(const ulonglong2*)(w + wld);    // k-pair 1
    #pragma unroll 2
    for (int k = 0; k < hin; k += 4) {
        int kn = (k + 4 < hin) ? (k + 4) : k;         // clamp prefetch at tail
        const ull* wn = Wp + (size_t)(kn >> 1) * wld + col2;
        ulonglong2 nw0 = *(const ulonglong2*)(wn);
        ulonglong2 nw1 = *(const ulonglong2*)(wn + wld);
        #pragma unroll
        for (int r = 0; r < 8; r++) {
            ulonglong2 x = *(const ulonglong2*)(ip + r * inS + k);
            fma2(acc[r][0], x.x, w0.x); fma2(acc[r][1], x.x, w0.y);
            fma2(acc[r][0], x.y, w1.x); fma2(acc[r][1], x.y, w1.y);
        }
        w0 = nw0; w1 = nw1;
    }
}

__device__ __forceinline__ void storeacc8(const ull acc[8][2], float* sOut,
                                          int outS, int col2, int rbase, bool g) {
    #pragma unroll
    for (int r = 0; r < 8; r++) {
        float v0 = fold(acc[r][0]), v1 = fold(acc[r][1]);
        if (g) { v0 = gelu_f(v0); v1 = gelu_f(v1); }
        *(float2*)(sOut + (rbase + r) * outS + col2) = make_float2(v0, v1);
    }
}

// ---------------- fused weight repack ----------------
__device__ __forceinline__ void rp_seg(const float* __restrict__ src,
                                       ull* __restrict__ dst, int rows2, int cols) {
    int idx = blockIdx.x * blockDim.x + threadIdx.x;
    int total = rows2 * cols;
    int stride = gridDim.x * blockDim.x;
    for (; idx < total; idx += stride) {
        int r2 = idx / cols, cc = idx - r2 * cols;
        dst[idx] = pk2(src[(size_t)(2 * r2) * cols + cc],
                       src[(size_t)(2 * r2 + 1) * cols + cc]);
    }
}

__global__ void repack_all(
    const float* We, const float* Wn, const float* Wm, const float* Wq,
    const float* Wo, const float* w1n, const float* w2n,
    const float* w1e, const float* w2e)
{
    switch (blockIdx.y) {
        case 0: rp_seg(We,  g_wp + OFF_WE,   512, 256); break;
        case 1: rp_seg(Wn,  g_wp + OFF_WN,  2048, 256); break;
        case 2: rp_seg(Wm,  g_wp + OFF_WM,  2048, 256); break;
        case 3: rp_seg(Wq,  g_wp + OFF_WQKV,1024, 768); break;
        case 4: rp_seg(Wo,  g_wp + OFF_WO,  1024, 256); break;
        case 5: rp_seg(w1n, g_wp + OFF_W1N, 1024, 512); break;
        case 6: rp_seg(w2n, g_wp + OFF_W2N, 2048, 256); break;
        case 7: rp_seg(w1e, g_wp + OFF_W1E, 1024, 512); break;
        case 8: rp_seg(w2e, g_wp + OFF_W2E, 2048, 256); break;
    }
}

// ---------------- gating kernel ----------------
__global__ void gate_kernel(const float* __restrict__ nf, const float* __restrict__ wg) {
    int n = blockIdx.x;
    int tid = threadIdx.x;
    float x = nf[n * HH + tid];
    float p[NE];
    #pragma unroll
    for (int e = 0; e < NE; e++) p[e] = x * wg[tid * NE + e];
    #pragma unroll
    for (int e = 0; e < NE; e++)
        #pragma unroll
        for (int o = 16; o; o >>= 1) p[e] += __shfl_xor_sync(0xffffffffu, p[e], o);
    __shared__ float logits[NE];
    if (tid < NE) logits[tid] = 0.f;
    __syncthreads();
    if ((tid & 31) == 0) {
        #pragma unroll
        for (int e = 0; e < NE; e++) atomicAdd(&logits[e], p[e]);
    }
    __syncthreads();
    if (tid == 0) {
        float v0 = -1e30f, v1 = -1e30f; int i0 = 0, i1 = 0;
        for (int e = 0; e < NE; e++) {
            float v = logits[e];
            if (v > v0) { v1 = v0; i1 = i0; v0 = v; i0 = e; }
            else if (v > v1) { v1 = v; i1 = e; }
        }
        float e1 = expf(v1 - v0);
        float g0 = 1.f / (1.f + e1);
        g_te[n * 2 + 0] = i0; g_te[n * 2 + 1] = i1;
        g_tg[n * 2 + 0] = g0; g_tg[n * 2 + 1] = 1.f - g0;
    }
}

// ---------------- main kernel: one CTA (512 thr) per node ----------------
__global__ __launch_bounds__(512) void moe_kernel(
    const float* __restrict__ node_features,
    const float* __restrict__ edge_features,
    const float* __restrict__ edge_raw,
    const int*   __restrict__ neighbor_list,
    const float* __restrict__ neighbor_mask,
    const float* __restrict__ attn_mask,
    const float* __restrict__ b_edge, const float* __restrict__ b_node,
    const float* __restrict__ b_msg,  const float* __restrict__ b_qkv,
    const float* __restrict__ b_out,
    const float* __restrict__ lag_, const float* __restrict__ lab_,
    const float* __restrict__ lfg_, const float* __restrict__ lfb_,
    const float* __restrict__ b1n, const float* __restrict__ b2n,
    const float* __restrict__ b1e, const float* __restrict__ b2e,
    float* __restrict__ out)
{
    extern __shared__ float sm[];
    float* sA   = sm;                 // KK*SS
    float* sB   = sA + KK * SS;
    float* sC   = sB + KK * SS;
    float* sD   = sC + KK * SS;
    float* sNh  = sD + KK * SS;       // HH
    float* sVec = sNh + HH;           // HH
    float* sHn  = sVec + HH;          // FF
    float* sMsk = sHn + FF;           // KK
    float* sAm  = sMsk + KK;          // KK
    float* sRed = sAm + KK;           // 16

    const int n = blockIdx.x;
    const int tid = threadIdx.x;
    const int lane = tid & 31, wid = tid >> 5;
    const int j = tid;                 // element index for <256 stages
    const int col2 = (tid & 127) * 2;  // adjacent output col pair
    const int rbase = (tid >> 7) * 8;  // 4 row groups of 8

    if (tid < KK) {
        sMsk[tid] = neighbor_mask[n * KK + tid];
        sAm[tid]  = attn_mask[n * KK + tid];
    }
    __syncthreads();
    float cnt = 0.f;
    #pragma unroll
    for (int k = 0; k < KK; k++) cnt += sMsk[k];
    float inv_cnt = 1.f / (cnt + 1e-5f);

    const float xj = (tid < HH) ? node_features[(size_t)n * HH + j] : 0.f;

    #pragma unroll 1
    for (int slot = 0; slot < 2; slot++) {
        int e = g_te[n * 2 + slot];
        float gate = g_tg[n * 2 + slot];
        const float* lag = lag_ + e * HH;
        const float* lab = lab_ + e * HH;
        const float* lfg = lfg_ + e * HH;
        const float* lfb = lfb_ + e * HH;

        // ---- recv layernorm -> sNh ----
        {
            float s = block_sum512(xj, sRed);
            float mu = s * (1.f / HH);
            float d = (tid < HH) ? (xj - mu) : 0.f;
            float q = block_sum512(d * d, sRed);
            float rs = rsqrtf(q * (1.f / HH) + 1e-5f);
            if (tid < HH) sNh[j] = d * rs * lag[j] + lab[j];
        }
        __syncthreads();

        // ---- rv = recv @ Wn_bottom + bn (warps 0-7) | edge_raw -> sB (warps 8-15) ----
        if (tid < HH) {
            const ull* W = g_wp + OFF_WN + (size_t)e * 65536u + 128u * 256u + j;
            ull a0 = pk2(b_node[e * HH + j], 0.f);
            ull a1 = pk2(0.f, 0.f), a2 = pk2(0.f, 0.f), a3 = pk2(0.f, 0.f);
            #pragma unroll 8
            for (int i = 0; i < 128; i += 4) {
                fma2(a0, *(const ull*)(sNh + 2 * i),     W[(size_t)i * 256]);
                fma2(a1, *(const ull*)(sNh + 2 * i + 2), W[(size_t)(i + 1) * 256]);
                fma2(a2, *(const ull*)(sNh + 2 * i + 4), W[(size_t)(i + 2) * 256]);
                fma2(a3, *(const ull*)(sNh + 2 * i + 6), W[(size_t)(i + 3) * 256]);
            }
            sVec[j] = fold(a0) + fold(a1) + fold(a2) + fold(a3);
        } else {
            int t2 = tid - 256;
            const float4* src = (const float4*)(edge_raw + (size_t)n * KK * DEn);
            float4* dst = (float4*)sB;
            #pragma unroll
            for (int i = 0; i < 4; i++) dst[t2 + 256 * i] = src[t2 + 256 * i];
        }
        __syncthreads();

        // ---- eh = gelu(edge_raw @ We + be) -> sA ----
        {
            ull acc[8][2];
            initacc8(acc, b_edge + e * HH, col2);
            gemm8x2(acc, sB, DEn, DEn, g_wp + OFF_WE + (size_t)e * 16384u, 256, col2, rbase);
            storeacc8(acc, sA, SS, col2, rbase, true);
        }
        __syncthreads();

        // ---- sender = LN(node_features[nbr]) -> sB (warp per row, 16 warps) ----
        for (int k = wid; k < KK; k += 16) {
            int nbr = neighbor_list[n * KK + k];
            const float* x = node_features + (size_t)nbr * HH;
            float v[8]; float s = 0.f;
            #pragma unroll
            for (int i = 0; i < 8; i++) { v[i] = x[lane + 32 * i]; s += v[i]; }
            #pragma unroll
            for (int o = 16; o; o >>= 1) s += __shfl_xor_sync(0xffffffffu, s, o);
            float mu = s * (1.f / HH);
            float q = 0.f;
            #pragma unroll
            for (int i = 0; i < 8; i++) { float d = v[i] - mu; q += d * d; }
            #pragma unroll
            for (int o = 16; o; o >>= 1) q += __shfl_xor_sync(0xffffffffu, q, o);
            float rs = rsqrtf(q * (1.f / HH) + 1e-5f);
            #pragma unroll
            for (int i = 0; i < 8; i++) {
                int cc = lane + 32 * i;
                sB[k * SS + cc] = (v[i] - mu) * rs * lag[cc] + lab[cc];
            }
        }
        __syncthreads();

        // ---- nodeh = gelu(sender@Wn_top + rv) -> sC ----
        {
            ull acc[8][2];
            initacc8(acc, sVec, col2);
            gemm8x2(acc, sB, SS, HH, g_wp + OFF_WN + (size_t)e * 65536u, 256, col2, rbase);
            storeacc8(acc, sC, SS, col2, rbase, true);
        }
        __syncthreads();

        // ---- msg = gelu(eh@Wm_top + nodeh@Wm_bot + bm) -> sB? (need sA,sC inputs) ----
        // write msg into sB (sender no longer needed)
        {
            const ull* Wt = g_wp + OFF_WM + (size_t)e * 65536u;
            ull acc[8][2];
            initacc8(acc, b_msg + e * HH, col2);
            gemm8x2(acc, sA, SS, HH, Wt, 256, col2, rbase);
            gemm8x2(acc, sC, SS, HH, Wt + 128u * 256u, 256, col2, rbase);
            storeacc8(acc, sB, SS, col2, rbase, true);
        }
        __syncthreads();

        // ---- qkv: q->sA, k->sC, v->sD ----
        {
            const ull* W = g_wp + OFF_WQKV + (size_t)e * 98304u;
            const float* bq = b_qkv + e * 3 * HH;
            float* dst0[3] = { sA, sC, sD };
            #pragma unroll 1
            for (int p = 0; p < 3; p++) {
                ull acc[8][2];
                initacc8(acc, bq + p * 256, col2);
                gemm8x2(acc, sB, SS, HH, W + p * 256, 768, col2, rbase);
                storeacc8(acc, dst0[p], SS, col2, rbase, false);
            }
        }
        __syncthreads();

        // ---- attention: warp = head (warps 0-7), lane = query. out -> sB ----
        if (wid < 8) {
            int h = wid;
            int a = lane;
            float qv[DHn];
            #pragma unroll
            for (int d = 0; d < DHn; d++) qv[d] = sA[a * SS + h * DHn + d];
            float sc[KK];
            const float scale = 0.17677669529663687f;   // 1/sqrt(32)
            #pragma unroll
            for (int b = 0; b < KK; b++) {
                float s = 0.f;
                #pragma unroll
                for (int d = 0; d < DHn; d++) s = fmaf(qv[d], sC[b * SS + h * DHn + d], s);
                sc[b] = s * scale + sAm[b];
            }
            float m = sc[0];
            #pragma unroll
            for (int b = 1; b < KK; b++) m = fmaxf(m, sc[b]);
            float ssum = 0.f;
            #pragma unroll
            for (int b = 0; b < KK; b++) { sc[b] = expf(sc[b] - m); ssum += sc[b]; }
            float inv = 1.f / ssum;
            float o[DHn];
            #pragma unroll
            for (int d = 0; d < DHn; d++) o[d] = 0.f;
            #pragma unroll
            for (int b = 0; b < KK; b++) {
                float p = sc[b] * inv;
                #pragma unroll
                for (int d = 0; d < DHn; d++) o[d] = fmaf(p, sD[b * SS + h * DHn + d], o[d]);
            }
            #pragma unroll
            for (int d = 0; d < DHn; d++) sB[a * SS + h * DHn + d] = o[d];
        }
        __syncthreads();

        // ---- edge_out = attn_out @ Wo + bo -> sD ----
        {
            ull acc[8][2];
            initacc8(acc, b_out + e * HH, col2);
            gemm8x2(acc, sB, SS, HH, g_wp + OFF_WO + (size_t)e * 32768u, 256, col2, rbase);
            storeacc8(acc, sD, SS, col2, rbase, false);
        }
        __syncthreads();

        // ---- prefetch edge_features into regs, masked-mean -> nfj ----
        float4 pf[4];
        {
            const float4* efsrc = (const float4*)(edge_features + (size_t)n * KK * HH);
            #pragma unroll
            for (int i = 0; i < 4; i++) pf[i] = efsrc[tid + 512 * i];
        }
        float nfj = 0.f;
        if (tid < HH) {
            float s = 0.f;
            #pragma unroll
            for (int k = 0; k < KK; k++) s += sD[k * SS + j] * sMsk[k];
            nfj = s * inv_cnt + xj;
        }
        __syncthreads();
        // ---- ef = edge_out + edge_features ----
        #pragma unroll
        for (int i = 0; i < 4; i++) {
            int idx = tid + 512 * i;          // float4 index, 64 per row
            int row = idx >> 6, c4 = (idx & 63) * 4;
            float4* d4 = (float4*)(sD + row * SS + c4);
            float4 v = *d4;
            v.x += pf[i].x; v.y += pf[i].y; v.z += pf[i].z; v.w += pf[i].w;
            *d4 = v;
        }
        __syncthreads();

        // ---- node FFN LN -> sVec ----
        {
            float s = block_sum512(nfj, sRed);
            float mu = s * (1.f / HH);
            float d = (tid < HH) ? (nfj - mu) : 0.f;
            float q = block_sum512(d * d, sRed);
            float rs = rsqrtf(q * (1.f / HH) + 1e-5f);
            if (tid < HH) sVec[j] = d * rs * lfg[j] + lfb[j];
        }
        __syncthreads();
        // ---- W1n: 512 outputs, one per thread ----
        {
            const ull* W = g_wp + OFF_W1N + (size_t)e * 65536u + tid;
            ull a0 = pk2(b1n[e * FF + tid], 0.f);
            ull a1 = pk2(0.f, 0.f), a2 = pk2(0.f, 0.f), a3 = pk2(0.f, 0.f);
            #pragma unroll 8
            for (int i = 0; i < 128; i += 4) {
                fma2(a0, *(const ull*)(sVec + 2 * i),     W[(size_t)i * 512]);
                fma2(a1, *(const ull*)(sVec + 2 * i + 2), W[(size_t)(i + 1) * 512]);
                fma2(a2, *(const ull*)(sVec + 2 * i + 4), W[(size_t)(i + 2) * 512]);
                fma2(a3, *(const ull*)(sVec + 2 * i + 6), W[(size_t)(i + 3) * 512]);
            }
            sHn[tid] = gelu_f(fold(a0) + fold(a1) + fold(a2) + fold(a3));
        }
        __syncthreads();

        // ---- W2n (warps 0-7) | edge LN: sD -> sA (warps 8-15) ----
        float node_final = 0.f;
        if (tid < HH) {
            const ull* W = g_wp + OFF_W2N + (size_t)e * 65536u + j;
            ull a0 = pk2(b2n[e * HH + j], 0.f);
            ull a1 = pk2(0.f, 0.f), a2 = pk2(0.f, 0.f), a3 = pk2(0.f, 0.f);
            #pragma unroll 8
            for (int i = 0; i < 256; i += 4) {
                fma2(a0, *(const ull*)(sHn + 2 * i),     W[(size_t)i * 256]);
                fma2(a1, *(const ull*)(sHn + 2 * i + 2), W[(size_t)(i + 1) * 256]);
                fma2(a2, *(const ull*)(sHn + 2 * i + 4), W[(size_t)(i + 2) * 256]);
                fma2(a3, *(const ull*)(sHn + 2 * i + 6), W[(size_t)(i + 3) * 256]);
            }
            node_final = nfj + fold(a0) + fold(a1) + fold(a2) + fold(a3);
        } else {
            for (int k = wid - 8; k < KK; k += 8) {
                float v[8]; float s = 0.f;
                #pragma unroll
                for (int i = 0; i < 8; i++) { v[i] = sD[k * SS + lane + 32 * i]; s += v[i]; }
                #pragma unroll
                for (int o = 16; o; o >>= 1) s += __shfl_xor_sync(0xffffffffu, s, o);
                float mu = s * (1.f / HH);
                float q = 0.f;
                #pragma unroll
                for (int i = 0; i < 8; i++) { float d = v[i] - mu; q += d * d; }
                #pragma unroll
                for (int o = 16; o; o >>= 1) q += __shfl_xor_sync(0xffffffffu, q, o);
                float rs = rsqrtf(q * (1.f / HH) + 1e-5f);
                #pragma unroll
                for (int i = 0; i < 8; i++) {
                    int cc = lane + 32 * i;
                    sA[k * SS + cc] = (v[i] - mu) * rs * lfg[cc] + lfb[cc];
                }
            }
        }
        __syncthreads();

        // ---- hidden_e halves: h0 -> sB (dims 0:256), h1 -> sC (dims 256:512) ----
        {
            const ull* W = g_wp + OFF_W1E + (size_t)e * 65536u;
            const float* bb = b1e + e * FF;
            {
                ull acc[8][2];
                initacc8(acc, bb, col2);
                gemm8x2(acc, sA, SS, HH, W, 512, col2, rbase);
                storeacc8(acc, sB, SS, col2, rbase, true);
            }
            {
                ull acc[8][2];
                initacc8(acc, bb + 256, col2);
                gemm8x2(acc, sA, SS, HH, W + 256, 512, col2, rbase);
                storeacc8(acc, sC, SS, col2, rbase, true);
            }
        }
        __syncthreads();

        // ---- ef_final = ef + [h0|h1] @ W2e + b2e ; write outputs ----
        {
            const ull* W = g_wp + OFF_W2E + (size_t)e * 65536u;
            ull acc[8][2];
            initacc8(acc, b2e + e * HH, col2);
            gemm8x2(acc, sB, SS, HH, W, 256, col2, rbase);
            gemm8x2(acc, sC, SS, HH, W + 128u * 256u, 256, col2, rbase);
            float* eout = out + (size_t)NN * HH + (size_t)n * KK * HH;
            if (slot == 0) {
                #pragma unroll
                for (int r = 0; r < 8; r++) {
                    int row = rbase + r;
                    float2 v = make_float2(
                        gate * (sD[row * SS + col2] + fold(acc[r][0])),
                        gate * (sD[row * SS + col2 + 1] + fold(acc[r][1])));
                    *(float2*)(eout + (size_t)row * HH + col2) = v;
                }
            } else {
                #pragma unroll
                for (int r = 0; r < 8; r++) {
                    int row = rbase + r;
                    float2* dst = (float2*)(eout + (size_t)row * HH + col2);
                    float2 v = *dst;
                    v.x += gate * (sD[row * SS + col2] + fold(acc[r][0]));
                    v.y += gate * (sD[row * SS + col2 + 1] + fold(acc[r][1]));
                    *dst = v;
                }
            }
        }
        if (tid < HH) {
            float* nout = out + (size_t)n * HH;
            if (slot == 0) nout[j] = gate * node_final;
            else           nout[j] += gate * node_final;
        }
        __syncthreads();   // buffers reused by next expert
    }
}

static constexpr int SMEM_FLOATS = 4 * KK * SS + HH + HH + FF + KK + KK + 16;
static constexpr int SMEM_BYTES  = SMEM_FLOATS * 4;

extern "C" void kernel_launch(void* const* d_in, const int* in_sizes, int n_in,
                              void* d_out, int out_size) {
    const float* node_features = (const float*)d_in[0];
    const float* edge_features = (const float*)d_in[1];
    const float* edge_raw      = (const float*)d_in[2];
    const int*   neighbor_list = (const int*)  d_in[3];
    const float* neighbor_mask = (const float*)d_in[4];
    const float* attn_mask     = (const float*)d_in[5];
    const float* w_gate        = (const float*)d_in[6];
    const float* W_edge = (const float*)d_in[7];
    const float* b_edge = (const float*)d_in[8];
    const float* W_node = (const float*)d_in[9];
    const float* b_node = (const float*)d_in[10];
    const float* W_msg  = (const float*)d_in[11];
    const float* b_msg  = (const float*)d_in[12];
    const float* W_qkv  = (const float*)d_in[13];
    const float* b_qkv  = (const float*)d_in[14];
    const float* W_out  = (const float*)d_in[15];
    const float* b_out  = (const float*)d_in[16];
    const float* lag    = (const float*)d_in[17];
    const float* lab    = (const float*)d_in[18];
    const float* lfg    = (const float*)d_in[19];
    const float* lfb    = (const float*)d_in[20];
    const float* W1n = (const float*)d_in[21];
    const float* b1n = (const float*)d_in[22];
    const float* W2n = (const float*)d_in[23];
    const float* b2n = (const float*)d_in[24];
    const float* W1e = (const float*)d_in[25];
    const float* b1e = (const float*)d_in[26];
    const float* W2e = (const float*)d_in[27];
    const float* b2e = (const float*)d_in[28];
    float* out = (float*)d_out;

    cudaFuncSetAttribute(moe_kernel, cudaFuncAttributeMaxDynamicSharedMemorySize, SMEM_BYTES);

    dim3 rg(128, 9);
    repack_all<<<rg, 256>>>(W_edge, W_node, W_msg, W_qkv, W_out, W1n, W2n, W1e, W2e);

    gate_kernel<<<NN, 256>>>(node_features, w_gate);

    moe_kernel<<<NN, 512, SMEM_BYTES>>>(
        node_features, edge_features, edge_raw, neighbor_list, neighbor_mask,
        attn_mask, b_edge, b_node, b_msg, b_qkv, b_out,
        lag, lab, lfg, lfb, b1n, b2n, b1e, b2e, out);
}

// round 5
// speedup vs baseline: 1.1282x; 1.1282x over previous
#include <cuda_runtime.h>
#include <math.h>

#define NN 1024
#define KK 32
#define HH 256
#define DEn 128
#define NE 8
#define NHn 8
#define DHn 32
#define FF 512
#define SS 260   // 16B-aligned padded slot stride

typedef unsigned long long ull;

__device__ int   g_te[NN * 2];
__device__ float g_tg[NN * 2];

// prepacked weights: k-pairs (W[k][j], W[k+1][j]) in one ull
#define OFF_WE   0u
#define OFF_WN   131072u
#define OFF_WM   655360u
#define OFF_WQKV 1179648u
#define OFF_WO   1966080u
#define OFF_W1N  2228224u
#define OFF_W2N  2752512u
#define OFF_W1E  3276800u
#define OFF_W2E  3801088u
#define WP_TOTAL 4325376u
__device__ ull g_wp[WP_TOTAL];

__device__ __forceinline__ float gelu_f(float x) {
    float x3 = x * x * x;
    return 0.5f * x * (1.0f + tanhf(0.7978845608028654f * (x + 0.044715f * x3)));
}
__device__ __forceinline__ ull pk2(float lo, float hi) {
    ull r; asm("mov.b64 %0,{%1,%2};" : "=l"(r) : "f"(lo), "f"(hi)); return r;
}
__device__ __forceinline__ void upk2(ull v, float& lo, float& hi) {
    asm("mov.b64 {%0,%1},%2;" : "=f"(lo), "=f"(hi) : "l"(v));
}
__device__ __forceinline__ void fma2(ull& d, ull a, ull b) {
    asm("fma.rn.f32x2 %0,%1,%2,%0;" : "+l"(d) : "l"(a), "l"(b));
}
__device__ __forceinline__ float fold(ull v) {
    float lo, hi; upk2(v, lo, hi); return lo + hi;
}

__device__ __forceinline__ float bsum256(float v, float* red) {
    #pragma unroll
    for (int o = 16; o; o >>= 1) v += __shfl_xor_sync(0xffffffffu, v, o);
    int tid = threadIdx.x;
    if ((tid & 31) == 0) red[tid >> 5] = v;
    __syncthreads();
    float s = red[0] + red[1] + red[2] + red[3] + red[4] + red[5] + red[6] + red[7];
    __syncthreads();
    return s;
}

// ---- 8-row x 4-adjacent-col f32x2 GEMM, k-pair step, depth-1 prefetch ----
__device__ __forceinline__ void initacc(ull acc[8][4], const float* bias, int cq) {
    float4 b = *(const float4*)(bias + cq);
    #pragma unroll
    for (int r = 0; r < 8; r++) {
        acc[r][0] = pk2(r == 0 ? b.x : 0.f, 0.f);
        acc[r][1] = pk2(r == 0 ? b.y : 0.f, 0.f);
        acc[r][2] = pk2(r == 0 ? b.z : 0.f, 0.f);
        acc[r][3] = pk2(r == 0 ? b.w : 0.f, 0.f);
    }
    // bias folded into row 0 only would be wrong; set all rows:
    #pragma unroll
    for (int r = 1; r < 8; r++) {
        acc[r][0] = pk2(b.x, 0.f); acc[r][1] = pk2(b.y, 0.f);
        acc[r][2] = pk2(b.z, 0.f); acc[r][3] = pk2(b.w, 0.f);
    }
}

__device__ __forceinline__ void gemm8x4(ull acc[8][4],
    const float* __restrict__ sIn, int inS, int hin,
    const ull* __restrict__ Wp, int wld, int cq, int rbase)
{
    const float* ip = sIn + rbase * inS;
    const ull* w = Wp + cq;
    ulonglong2 w0 = *(const ulonglong2*)w;
    ulonglong2 w1 = *(const ulonglong2*)(w + 2);
    #pragma unroll 2
    for (int k = 0; k < hin; k += 2) {
        int kn = (k + 2 < hin) ? (k + 2) : k;
        const ull* wn = Wp + (size_t)(kn >> 1) * wld + cq;
        ulonglong2 n0 = *(const ulonglong2*)wn;
        ulonglong2 n1 = *(const ulonglong2*)(wn + 2);
        #pragma unroll
        for (int r = 0; r < 8; r++) {
            ull x = *(const ull*)(ip + r * inS + k);
            fma2(acc[r][0], x, w0.x); fma2(acc[r][1], x, w0.y);
            fma2(acc[r][2], x, w1.x); fma2(acc[r][3], x, w1.y);
        }
        w0 = n0; w1 = n1;
    }
}

__device__ __forceinline__ void storeacc(const ull acc[8][4], float* sOut,
                                         int outS, int cq, int rbase, bool g) {
    #pragma unroll
    for (int r = 0; r < 8; r++) {
        float4 v;
        v.x = fold(acc[r][0]); v.y = fold(acc[r][1]);
        v.z = fold(acc[r][2]); v.w = fold(acc[r][3]);
        if (g) { v.x = gelu_f(v.x); v.y = gelu_f(v.y); v.z = gelu_f(v.z); v.w = gelu_f(v.w); }
        *(float4*)(sOut + (rbase + r) * outS + cq) = v;
    }
}

// ---------------- fused weight repack ----------------
__device__ __forceinline__ void rp_seg(const float* __restrict__ src,
                                       ull* __restrict__ dst, int rows2, int cols) {
    int idx = blockIdx.x * blockDim.x + threadIdx.x;
    int total = rows2 * cols;
    int stride = gridDim.x * blockDim.x;
    for (; idx < total; idx += stride) {
        int r2 = idx / cols, cc = idx - r2 * cols;
        dst[idx] = pk2(src[(size_t)(2 * r2) * cols + cc],
                       src[(size_t)(2 * r2 + 1) * cols + cc]);
    }
}

__global__ void repack_all(
    const float* We, const float* Wn, const float* Wm, const float* Wq,
    const float* Wo, const float* w1n, const float* w2n,
    const float* w1e, const float* w2e)
{
    switch (blockIdx.y) {
        case 0: rp_seg(We,  g_wp + OFF_WE,   512, 256); break;
        case 1: rp_seg(Wn,  g_wp + OFF_WN,  2048, 256); break;
        case 2: rp_seg(Wm,  g_wp + OFF_WM,  2048, 256); break;
        case 3: rp_seg(Wq,  g_wp + OFF_WQKV,1024, 768); break;
        case 4: rp_seg(Wo,  g_wp + OFF_WO,  1024, 256); break;
        case 5: rp_seg(w1n, g_wp + OFF_W1N, 1024, 512); break;
        case 6: rp_seg(w2n, g_wp + OFF_W2N, 2048, 256); break;
        case 7: rp_seg(w1e, g_wp + OFF_W1E, 1024, 512); break;
        case 8: rp_seg(w2e, g_wp + OFF_W2E, 2048, 256); break;
    }
}

// ---------------- zero output ----------------
__global__ void zero_kernel(float4* __restrict__ p, int n4) {
    int idx = blockIdx.x * blockDim.x + threadIdx.x;
    int stride = gridDim.x * blockDim.x;
    float4 z = make_float4(0.f, 0.f, 0.f, 0.f);
    for (; idx < n4; idx += stride) p[idx] = z;
}

// ---------------- gating kernel ----------------
__global__ void gate_kernel(const float* __restrict__ nf, const float* __restrict__ wg) {
    int n = blockIdx.x;
    int tid = threadIdx.x;
    float x = nf[n * HH + tid];
    float p[NE];
    #pragma unroll
    for (int e = 0; e < NE; e++) p[e] = x * wg[tid * NE + e];
    #pragma unroll
    for (int e = 0; e < NE; e++)
        #pragma unroll
        for (int o = 16; o; o >>= 1) p[e] += __shfl_xor_sync(0xffffffffu, p[e], o);
    __shared__ float logits[NE];
    if (tid < NE) logits[tid] = 0.f;
    __syncthreads();
    if ((tid & 31) == 0) {
        #pragma unroll
        for (int e = 0; e < NE; e++) atomicAdd(&logits[e], p[e]);
    }
    __syncthreads();
    if (tid == 0) {
        float v0 = -1e30f, v1 = -1e30f; int i0 = 0, i1 = 0;
        for (int e = 0; e < NE; e++) {
            float v = logits[e];
            if (v > v0) { v1 = v0; i1 = i0; v0 = v; i0 = e; }
            else if (v > v1) { v1 = v; i1 = e; }
        }
        float e1 = __expf(v1 - v0);
        float g0 = 1.f / (1.f + e1);
        g_te[n * 2 + 0] = i0; g_te[n * 2 + 1] = i1;
        g_tg[n * 2 + 0] = g0; g_tg[n * 2 + 1] = 1.f - g0;
    }
}

// ---------------- main kernel: one CTA (256 thr) per (node, slot) ----------------
__global__ __launch_bounds__(256, 2) void moe_kernel(
    const float* __restrict__ node_features,
    const float* __restrict__ edge_features,
    const float* __restrict__ edge_raw,
    const int*   __restrict__ neighbor_list,
    const float* __restrict__ neighbor_mask,
    const float* __restrict__ attn_mask,
    const float* __restrict__ b_edge, const float* __restrict__ b_node,
    const float* __restrict__ b_msg,  const float* __restrict__ b_qkv,
    const float* __restrict__ b_out,
    const float* __restrict__ lag_, const float* __restrict__ lab_,
    const float* __restrict__ lfg_, const float* __restrict__ lfb_,
    const float* __restrict__ b1n, const float* __restrict__ b2n,
    const float* __restrict__ b1e, const float* __restrict__ b2e,
    float* __restrict__ out)
{
    extern __shared__ float sm[];
    float* sA   = sm;                 // KK*SS
    float* sB   = sA + KK * SS;
    float* sC   = sB + KK * SS;
    float* sNh  = sC + KK * SS;       // HH
    float* sVec = sNh + HH;           // HH
    float* sHn  = sVec + HH;          // FF
    float* sMsk = sHn + FF;           // KK
    float* sAm  = sMsk + KK;          // KK
    float* sRed = sAm + KK;           // 8

    const int n = blockIdx.x;
    const int slot = blockIdx.y;
    const int tid = threadIdx.x;
    const int lane = tid & 31, wid = tid >> 5;
    const int j = tid;
    const int cq = (tid & 63) * 4;     // 4 adjacent output cols
    const int rbase = (tid >> 6) * 8;  // 8 rows

    const int e = g_te[n * 2 + slot];
    const float gate = g_tg[n * 2 + slot];
    const float* lag = lag_ + e * HH;
    const float* lab = lab_ + e * HH;
    const float* lfg = lfg_ + e * HH;
    const float* lfb = lfb_ + e * HH;

    if (tid < KK) {
        sMsk[tid] = neighbor_mask[n * KK + tid];
        sAm[tid]  = attn_mask[n * KK + tid];
    }
    __syncthreads();
    float cnt = 0.f;
    #pragma unroll
    for (int k = 0; k < KK; k++) cnt += sMsk[k];
    float inv_cnt = 1.f / (cnt + 1e-5f);

    const float xj = node_features[(size_t)n * HH + j];

    // ---- recv layernorm -> sNh ----
    {
        float s = bsum256(xj, sRed);
        float mu = s * (1.f / HH);
        float d = xj - mu;
        float q = bsum256(d * d, sRed);
        float rs = rsqrtf(q * (1.f / HH) + 1e-5f);
        sNh[j] = d * rs * lag[j] + lab[j];
    }
    __syncthreads();

    // ---- edge_raw -> sA (32x128 dense) ----
    {
        const float4* src = (const float4*)(edge_raw + (size_t)n * KK * DEn);
        float4* dst = (float4*)sA;
        #pragma unroll
        for (int i = 0; i < 4; i++) dst[tid + 256 * i] = src[tid + 256 * i];
    }
    // ---- rv = recv @ Wn_bottom + bn -> sVec ----
    {
        const ull* W = g_wp + OFF_WN + (size_t)e * 65536u + 128u * 256u + j;
        ull a0 = pk2(b_node[e * HH + j], 0.f);
        ull a1 = pk2(0.f, 0.f), a2 = pk2(0.f, 0.f), a3 = pk2(0.f, 0.f);
        #pragma unroll 8
        for (int i = 0; i < 128; i += 4) {
            fma2(a0, *(const ull*)(sNh + 2 * i),     W[(size_t)i * 256]);
            fma2(a1, *(const ull*)(sNh + 2 * i + 2), W[(size_t)(i + 1) * 256]);
            fma2(a2, *(const ull*)(sNh + 2 * i + 4), W[(size_t)(i + 2) * 256]);
            fma2(a3, *(const ull*)(sNh + 2 * i + 6), W[(size_t)(i + 3) * 256]);
        }
        sVec[j] = fold(a0) + fold(a1) + fold(a2) + fold(a3);
    }
    __syncthreads();

    // ---- eh = gelu(edge_raw(sA) @ We + be) -> sB ----
    {
        ull acc[8][4];
        initacc(acc, b_edge + e * HH, cq);
        gemm8x4(acc, sA, DEn, DEn, g_wp + OFF_WE + (size_t)e * 16384u, 256, cq, rbase);
        storeacc(acc, sB, SS, cq, rbase, true);
    }
    __syncthreads();

    // ---- sender = LN(node_features[nbr]) -> sA ----
    for (int k = wid; k < KK; k += 8) {
        int nbr = neighbor_list[n * KK + k];
        const float* x = node_features + (size_t)nbr * HH;
        float v[8]; float s = 0.f;
        #pragma unroll
        for (int i = 0; i < 8; i++) { v[i] = x[lane + 32 * i]; s += v[i]; }
        #pragma unroll
        for (int o = 16; o; o >>= 1) s += __shfl_xor_sync(0xffffffffu, s, o);
        float mu = s * (1.f / HH);
        float q = 0.f;
        #pragma unroll
        for (int i = 0; i < 8; i++) { float d = v[i] - mu; q += d * d; }
        #pragma unroll
        for (int o = 16; o; o >>= 1) q += __shfl_xor_sync(0xffffffffu, q, o);
        float rs = rsqrtf(q * (1.f / HH) + 1e-5f);
        #pragma unroll
        for (int i = 0; i < 8; i++) {
            int cc = lane + 32 * i;
            sA[k * SS + cc] = (v[i] - mu) * rs * lag[cc] + lab[cc];
        }
    }
    __syncthreads();

    // ---- nodeh = gelu(sender(sA)@Wn_top + rv) -> sC ----
    {
        ull acc[8][4];
        initacc(acc, sVec, cq);
        gemm8x4(acc, sA, SS, HH, g_wp + OFF_WN + (size_t)e * 65536u, 256, cq, rbase);
        storeacc(acc, sC, SS, cq, rbase, true);
    }
    __syncthreads();

    // ---- msg = gelu(eh(sB)@Wm_top + nodeh(sC)@Wm_bot + bm) -> sA ----
    {
        const ull* Wt = g_wp + OFF_WM + (size_t)e * 65536u;
        ull acc[8][4];
        initacc(acc, b_msg + e * HH, cq);
        gemm8x4(acc, sB, SS, HH, Wt, 256, cq, rbase);
        gemm8x4(acc, sC, SS, HH, Wt + 128u * 256u, 256, cq, rbase);
        storeacc(acc, sA, SS, cq, rbase, true);
    }
    __syncthreads();

    // ---- qkv from msg(sA): q->sB, k->sC, v->sA (in-place after barrier) ----
    {
        const ull* W = g_wp + OFF_WQKV + (size_t)e * 98304u;
        const float* bq = b_qkv + e * 3 * HH;
        {
            ull acc[8][4];
            initacc(acc, bq, cq);
            gemm8x4(acc, sA, SS, HH, W, 768, cq, rbase);
            storeacc(acc, sB, SS, cq, rbase, false);
        }
        {
            ull acc[8][4];
            initacc(acc, bq + 256, cq);
            gemm8x4(acc, sA, SS, HH, W + 256, 768, cq, rbase);
            storeacc(acc, sC, SS, cq, rbase, false);
        }
        {
            ull acc[8][4];
            initacc(acc, bq + 512, cq);
            gemm8x4(acc, sA, SS, HH, W + 512, 768, cq, rbase);
            __syncthreads();                  // all reads of msg complete
            storeacc(acc, sA, SS, cq, rbase, false);
        }
    }
    __syncthreads();

    // ---- attention: warp = head, lane = query. q(sB), k(sC), v(sA) -> sB ----
    {
        int h = wid;
        int a = lane;
        float qv[DHn];
        #pragma unroll
        for (int d = 0; d < DHn; d++) qv[d] = sB[a * SS + h * DHn + d];
        float sc[KK];
        const float scale = 0.17677669529663687f;   // 1/sqrt(32)
        #pragma unroll
        for (int b = 0; b < KK; b++) {
            float s = 0.f;
            #pragma unroll
            for (int d = 0; d < DHn; d++) s = fmaf(qv[d], sC[b * SS + h * DHn + d], s);
            sc[b] = s * scale + sAm[b];
        }
        float m = sc[0];
        #pragma unroll
        for (int b = 1; b < KK; b++) m = fmaxf(m, sc[b]);
        float ssum = 0.f;
        #pragma unroll
        for (int b = 0; b < KK; b++) { sc[b] = __expf(sc[b] - m); ssum += sc[b]; }
        float inv = 1.f / ssum;
        float o[DHn];
        #pragma unroll
        for (int d = 0; d < DHn; d++) o[d] = 0.f;
        #pragma unroll
        for (int b = 0; b < KK; b++) {
            float p = sc[b] * inv;
            #pragma unroll
            for (int d = 0; d < DHn; d++) o[d] = fmaf(p, sA[b * SS + h * DHn + d], o[d]);
        }
        #pragma unroll
        for (int d = 0; d < DHn; d++) sB[a * SS + h * DHn + d] = o[d];
    }
    __syncthreads();

    // ---- edge_out = attn_out(sB) @ Wo + bo -> sC ----
    {
        ull acc[8][4];
        initacc(acc, b_out + e * HH, cq);
        gemm8x4(acc, sB, SS, HH, g_wp + OFF_WO + (size_t)e * 32768u, 256, cq, rbase);
        storeacc(acc, sC, SS, cq, rbase, false);
    }
    __syncthreads();

    // ---- masked-mean aggregate -> nfj ----
    float nfj;
    {
        float s = 0.f;
        #pragma unroll
        for (int k = 0; k < KK; k++) s += sC[k * SS + j] * sMsk[k];
        nfj = s * inv_cnt + xj;
    }
    __syncthreads();
    // ---- ef = edge_out + edge_features (RMW sC) ----
    {
        const float4* efsrc = (const float4*)(edge_features + (size_t)n * KK * HH);
        #pragma unroll
        for (int i = 0; i < 8; i++) {
            int idx = tid + 256 * i;           // float4 idx, 64 per row
            int row = idx >> 6, c4 = (idx & 63) * 4;
            float4* d4 = (float4*)(sC + row * SS + c4);
            float4 v = *d4;
            float4 a = efsrc[idx];
            v.x += a.x; v.y += a.y; v.z += a.z; v.w += a.w;
            *d4 = v;
        }
    }
    __syncthreads();

    // ---- node FFN LN -> sVec ----
    {
        float s = bsum256(nfj, sRed);
        float mu = s * (1.f / HH);
        float d = nfj - mu;
        float q = bsum256(d * d, sRed);
        float rs = rsqrtf(q * (1.f / HH) + 1e-5f);
        sVec[j] = d * rs * lfg[j] + lfb[j];
    }
    __syncthreads();
    // ---- W1n: 2 outputs per thread ----
    {
        const ull* W = g_wp + OFF_W1N + (size_t)e * 65536u;
        ull a0 = pk2(b1n[e * FF + tid], 0.f), a1 = pk2(0.f, 0.f);
        ull c0 = pk2(b1n[e * FF + tid + 256], 0.f), c1 = pk2(0.f, 0.f);
        #pragma unroll 8
        for (int i = 0; i < 128; i += 2) {
            ull x0 = *(const ull*)(sVec + 2 * i);
            ull x1 = *(const ull*)(sVec + 2 * i + 2);
            fma2(a0, x0, W[(size_t)i * 512 + tid]);
            fma2(c0, x0, W[(size_t)i * 512 + tid + 256]);
            fma2(a1, x1, W[(size_t)(i + 1) * 512 + tid]);
            fma2(c1, x1, W[(size_t)(i + 1) * 512 + tid + 256]);
        }
        sHn[tid]       = gelu_f(fold(a0) + fold(a1));
        sHn[tid + 256] = gelu_f(fold(c0) + fold(c1));
    }
    __syncthreads();
    // ---- W2n -> node_final ----
    float node_final;
    {
        const ull* W = g_wp + OFF_W2N + (size_t)e * 65536u + j;
        ull a0 = pk2(b2n[e * HH + j], 0.f);
        ull a1 = pk2(0.f, 0.f), a2 = pk2(0.f, 0.f), a3 = pk2(0.f, 0.f);
        #pragma unroll 8
        for (int i = 0; i < 256; i += 4) {
            fma2(a0, *(const ull*)(sHn + 2 * i),     W[(size_t)i * 256]);
            fma2(a1, *(const ull*)(sHn + 2 * i + 2), W[(size_t)(i + 1) * 256]);
            fma2(a2, *(const ull*)(sHn + 2 * i + 4), W[(size_t)(i + 2) * 256]);
            fma2(a3, *(const ull*)(sHn + 2 * i + 6), W[(size_t)(i + 3) * 256]);
        }
        node_final = nfj + fold(a0) + fold(a1) + fold(a2) + fold(a3);
    }

    // ---- edge FFN: eh2 = LN(ef(sC)) -> sA ----
    for (int k = wid; k < KK; k += 8) {
        float v[8]; float s = 0.f;
        #pragma unroll
        for (int i = 0; i < 8; i++) { v[i] = sC[k * SS + lane + 32 * i]; s += v[i]; }
        #pragma unroll
        for (int o = 16; o; o >>= 1) s += __shfl_xor_sync(0xffffffffu, s, o);
        float mu = s * (1.f / HH);
        float q = 0.f;
        #pragma unroll
        for (int i = 0; i < 8; i++) { float d = v[i] - mu; q += d * d; }
        #pragma unroll
        for (int o = 16; o; o >>= 1) q += __shfl_xor_sync(0xffffffffu, q, o);
        float rs = rsqrtf(q * (1.f / HH) + 1e-5f);
        #pragma unroll
        for (int i = 0; i < 8; i++) {
            int cc = lane + 32 * i;
            sA[k * SS + cc] = (v[i] - mu) * rs * lfg[cc] + lfb[cc];
        }
    }
    __syncthreads();

    // ---- hidden0 = gelu(eh2(sA)@W1e[:, :256]) -> sB ----
    {
        ull acc[8][4];
        initacc(acc, b1e + e * FF, cq);
        gemm8x4(acc, sA, SS, HH, g_wp + OFF_W1E + (size_t)e * 65536u, 512, cq, rbase);
        storeacc(acc, sB, SS, cq, rbase, true);
    }
    __syncthreads();
    // ---- sC += b2e + hidden0(sB) @ W2e_top ----
    {
        ull acc[8][4];
        initacc(acc, b2e + e * HH, cq);
        gemm8x4(acc, sB, SS, HH, g_wp + OFF_W2E + (size_t)e * 65536u, 256, cq, rbase);
        #pragma unroll
        for (int r = 0; r < 8; r++) {
            float4* d4 = (float4*)(sC + (rbase + r) * SS + cq);
            float4 v = *d4;
            v.x += fold(acc[r][0]); v.y += fold(acc[r][1]);
            v.z += fold(acc[r][2]); v.w += fold(acc[r][3]);
            *d4 = v;
        }
    }
    __syncthreads();
    // ---- hidden1 = gelu(eh2(sA)@W1e[:, 256:]) -> sB ----
    {
        ull acc[8][4];
        initacc(acc, b1e + e * FF + 256, cq);
        gemm8x4(acc, sA, SS, HH, g_wp + OFF_W1E + (size_t)e * 65536u + 256, 512, cq, rbase);
        storeacc(acc, sB, SS, cq, rbase, true);
    }
    __syncthreads();
    // ---- final = sC + hidden1(sB)@W2e_bot ; atomic write ----
    {
        ull acc[8][4];
        #pragma unroll
        for (int r = 0; r < 8; r++)
            #pragma unroll
            for (int t = 0; t < 4; t++) acc[r][t] = pk2(0.f, 0.f);
        gemm8x4(acc, sB, SS, HH, g_wp + OFF_W2E + (size_t)e * 65536u + 128u * 256u,
                256, cq, rbase);
        float* eout = out + (size_t)NN * HH + (size_t)n * KK * HH;
        #pragma unroll
        for (int r = 0; r < 8; r++) {
            int row = rbase + r;
            const float* c = sC + row * SS + cq;
            float* o = eout + (size_t)row * HH + cq;
            atomicAdd(o + 0, gate * (c[0] + fold(acc[r][0])));
            atomicAdd(o + 1, gate * (c[1] + fold(acc[r][1])));
            atomicAdd(o + 2, gate * (c[2] + fold(acc[r][2])));
            atomicAdd(o + 3, gate * (c[3] + fold(acc[r][3])));
        }
    }
    atomicAdd(out + (size_t)n * HH + j, gate * node_final);
}

static constexpr int SMEM_FLOATS = 3 * KK * SS + HH + HH + FF + KK + KK + 8;
static constexpr int SMEM_BYTES  = SMEM_FLOATS * 4;

extern "C" void kernel_launch(void* const* d_in, const int* in_sizes, int n_in,
                              void* d_out, int out_size) {
    const float* node_features = (const float*)d_in[0];
    const float* edge_features = (const float*)d_in[1];
    const float* edge_raw      = (const float*)d_in[2];
    const int*   neighbor_list = (const int*)  d_in[3];
    const float* neighbor_mask = (const float*)d_in[4];
    const float* attn_mask     = (const float*)d_in[5];
    const float* w_gate        = (const float*)d_in[6];
    const float* W_edge = (const float*)d_in[7];
    const float* b_edge = (const float*)d_in[8];
    const float* W_node = (const float*)d_in[9];
    const float* b_node = (const float*)d_in[10];
    const float* W_msg  = (const float*)d_in[11];
    const float* b_msg  = (const float*)d_in[12];
    const float* W_qkv  = (const float*)d_in[13];
    const float* b_qkv  = (const float*)d_in[14];
    const float* W_out  = (const float*)d_in[15];
    const float* b_out  = (const float*)d_in[16];
    const float* lag    = (const float*)d_in[17];
    const float* lab    = (const float*)d_in[18];
    const float* lfg    = (const float*)d_in[19];
    const float* lfb    = (const float*)d_in[20];
    const float* W1n = (const float*)d_in[21];
    const float* b1n = (const float*)d_in[22];
    const float* W2n = (const float*)d_in[23];
    const float* b2n = (const float*)d_in[24];
    const float* W1e = (const float*)d_in[25];
    const float* b1e = (const float*)d_in[26];
    const float* W2e = (const float*)d_in[27];
    const float* b2e = (const float*)d_in[28];
    float* out = (float*)d_out;

    cudaFuncSetAttribute(moe_kernel, cudaFuncAttributeMaxDynamicSharedMemorySize, SMEM_BYTES);

    dim3 rg(128, 9);
    repack_all<<<rg, 256>>>(W_edge, W_node, W_msg, W_qkv, W_out, W1n, W2n, W1e, W2e);
    gate_kernel<<<NN, 256>>>(node_features, w_gate);
    zero_kernel<<<512, 256>>>((float4*)out, out_size / 4);

    dim3 grid(NN, 2);
    moe_kernel<<<grid, 256, SMEM_BYTES>>>(
        node_features, edge_features, edge_raw, neighbor_list, neighbor_mask,
        attn_mask, b_edge, b_node, b_msg, b_qkv, b_out,
        lag, lab, lfg, lfb, b1n, b2n, b1e, b2e, out);
}

// round 6
// speedup vs baseline: 1.1427x; 1.0128x over previous
#include <cuda_runtime.h>
#include <math.h>

#define NN 1024
#define KK 32
#define HH 256
#define DEn 128
#define NE 8
#define NHn 8
#define DHn 32
#define FF 512
#define SS 260   // 16B-aligned padded slot stride

typedef unsigned long long ull;

__device__ int   g_te[NN * 2];
__device__ float g_tg[NN * 2];

// prepacked weights: k-pairs (W[k][j], W[k+1][j]) in one ull
#define OFF_WE   0u
#define OFF_WN   131072u
#define OFF_WM   655360u
#define OFF_WQKV 1179648u
#define OFF_WO   1966080u
#define OFF_W1N  2228224u
#define OFF_W2N  2752512u
#define OFF_W1E  3276800u
#define OFF_W2E  3801088u
#define WP_TOTAL 4325376u
__device__ ull g_wp[WP_TOTAL];

__device__ __forceinline__ float gelu_f(float x) {
    float u = 0.7978845608028654f * (x + 0.044715f * x * x * x);
    float e = __expf(2.f * u);
    float t = 1.f - __fdividef(2.f, e + 1.f);
    return 0.5f * x * (1.f + t);
}
__device__ __forceinline__ ull pk2(float lo, float hi) {
    ull r; asm("mov.b64 %0,{%1,%2};" : "=l"(r) : "f"(lo), "f"(hi)); return r;
}
__device__ __forceinline__ void upk2(ull v, float& lo, float& hi) {
    asm("mov.b64 {%0,%1},%2;" : "=f"(lo), "=f"(hi) : "l"(v));
}
__device__ __forceinline__ void fma2(ull& d, ull a, ull b) {
    asm("fma.rn.f32x2 %0,%1,%2,%0;" : "+l"(d) : "l"(a), "l"(b));
}
__device__ __forceinline__ float fold(ull v) {
    float lo, hi; upk2(v, lo, hi); return lo + hi;
}

__device__ __forceinline__ float bsum256(float v, float* red) {
    #pragma unroll
    for (int o = 16; o; o >>= 1) v += __shfl_xor_sync(0xffffffffu, v, o);
    int tid = threadIdx.x;
    if ((tid & 31) == 0) red[tid >> 5] = v;
    __syncthreads();
    float s = red[0] + red[1] + red[2] + red[3] + red[4] + red[5] + red[6] + red[7];
    __syncthreads();
    return s;
}

// ---- 8-row x 4-col f32x2 GEMM, 4-k step, LDS.128 inputs, ptr-bump + prefetch ----
__device__ __forceinline__ void initacc(ull acc[8][4], const float* bias, int cq) {
    float4 b = *(const float4*)(bias + cq);
    ull b0 = pk2(b.x, 0.f), b1 = pk2(b.y, 0.f), b2 = pk2(b.z, 0.f), b3 = pk2(b.w, 0.f);
    #pragma unroll
    for (int r = 0; r < 8; r++) {
        acc[r][0] = b0; acc[r][1] = b1; acc[r][2] = b2; acc[r][3] = b3;
    }
}

__device__ __forceinline__ void gemm8x4(ull acc[8][4],
    const float* __restrict__ sIn, int inS, int hin,
    const ull* __restrict__ Wp, int wld, int cq, int rbase)
{
    const float* ip = sIn + rbase * inS;
    const ull* w = Wp + cq;
    // weights for k-pairs 0 and 1
    ulonglong2 wa0 = *(const ulonglong2*)w;
    ulonglong2 wa1 = *(const ulonglong2*)(w + 2);
    ulonglong2 wb0 = *(const ulonglong2*)(w + wld);
    ulonglong2 wb1 = *(const ulonglong2*)(w + wld + 2);
    w += 2 * wld;
    #pragma unroll 1
    for (int k = 0; k < hin - 4; k += 4) {
        ulonglong2 na0 = *(const ulonglong2*)w;
        ulonglong2 na1 = *(const ulonglong2*)(w + 2);
        ulonglong2 nb0 = *(const ulonglong2*)(w + wld);
        ulonglong2 nb1 = *(const ulonglong2*)(w + wld + 2);
        w += 2 * wld;
        #pragma unroll
        for (int r = 0; r < 8; r++) {
            ulonglong2 x = *(const ulonglong2*)(ip + r * inS + k);   // k..k+3
            fma2(acc[r][0], x.x, wa0.x); fma2(acc[r][1], x.x, wa0.y);
            fma2(acc[r][2], x.x, wa1.x); fma2(acc[r][3], x.x, wa1.y);
            fma2(acc[r][0], x.y, wb0.x); fma2(acc[r][1], x.y, wb0.y);
            fma2(acc[r][2], x.y, wb1.x); fma2(acc[r][3], x.y, wb1.y);
        }
        wa0 = na0; wa1 = na1; wb0 = nb0; wb1 = nb1;
    }
    {
        const int k = hin - 4;
        #pragma unroll
        for (int r = 0; r < 8; r++) {
            ulonglong2 x = *(const ulonglong2*)(ip + r * inS + k);
            fma2(acc[r][0], x.x, wa0.x); fma2(acc[r][1], x.x, wa0.y);
            fma2(acc[r][2], x.x, wa1.x); fma2(acc[r][3], x.x, wa1.y);
            fma2(acc[r][0], x.y, wb0.x); fma2(acc[r][1], x.y, wb0.y);
            fma2(acc[r][2], x.y, wb1.x); fma2(acc[r][3], x.y, wb1.y);
        }
    }
}

__device__ __forceinline__ void storeacc(const ull acc[8][4], float* sOut,
                                         int outS, int cq, int rbase, bool g) {
    #pragma unroll
    for (int r = 0; r < 8; r++) {
        float4 v;
        v.x = fold(acc[r][0]); v.y = fold(acc[r][1]);
        v.z = fold(acc[r][2]); v.w = fold(acc[r][3]);
        if (g) { v.x = gelu_f(v.x); v.y = gelu_f(v.y); v.z = gelu_f(v.z); v.w = gelu_f(v.w); }
        *(float4*)(sOut + (rbase + r) * outS + cq) = v;
    }
}

// ---------------- fused weight repack ----------------
__device__ __forceinline__ void rp_seg(const float* __restrict__ src,
                                       ull* __restrict__ dst, int rows2, int cols) {
    int idx = blockIdx.x * blockDim.x + threadIdx.x;
    int total = rows2 * cols;
    int stride = gridDim.x * blockDim.x;
    for (; idx < total; idx += stride) {
        int r2 = idx / cols, cc = idx - r2 * cols;
        dst[idx] = pk2(src[(size_t)(2 * r2) * cols + cc],
                       src[(size_t)(2 * r2 + 1) * cols + cc]);
    }
}

__global__ void repack_all(
    const float* We, const float* Wn, const float* Wm, const float* Wq,
    const float* Wo, const float* w1n, const float* w2n,
    const float* w1e, const float* w2e)
{
    switch (blockIdx.y) {
        case 0: rp_seg(We,  g_wp + OFF_WE,   512, 256); break;
        case 1: rp_seg(Wn,  g_wp + OFF_WN,  2048, 256); break;
        case 2: rp_seg(Wm,  g_wp + OFF_WM,  2048, 256); break;
        case 3: rp_seg(Wq,  g_wp + OFF_WQKV,1024, 768); break;
        case 4: rp_seg(Wo,  g_wp + OFF_WO,  1024, 256); break;
        case 5: rp_seg(w1n, g_wp + OFF_W1N, 1024, 512); break;
        case 6: rp_seg(w2n, g_wp + OFF_W2N, 2048, 256); break;
        case 7: rp_seg(w1e, g_wp + OFF_W1E, 1024, 512); break;
        case 8: rp_seg(w2e, g_wp + OFF_W2E, 2048, 256); break;
    }
}

// ---------------- zero output ----------------
__global__ void zero_kernel(float4* __restrict__ p, int n4) {
    int idx = blockIdx.x * blockDim.x + threadIdx.x;
    int stride = gridDim.x * blockDim.x;
    float4 z = make_float4(0.f, 0.f, 0.f, 0.f);
    for (; idx < n4; idx += stride) p[idx] = z;
}

// ---------------- gating kernel ----------------
__global__ void gate_kernel(const float* __restrict__ nf, const float* __restrict__ wg) {
    int n = blockIdx.x;
    int tid = threadIdx.x;
    float x = nf[n * HH + tid];
    float p[NE];
    #pragma unroll
    for (int e = 0; e < NE; e++) p[e] = x * wg[tid * NE + e];
    #pragma unroll
    for (int e = 0; e < NE; e++)
        #pragma unroll
        for (int o = 16; o; o >>= 1) p[e] += __shfl_xor_sync(0xffffffffu, p[e], o);
    __shared__ float logits[NE];
    if (tid < NE) logits[tid] = 0.f;
    __syncthreads();
    if ((tid & 31) == 0) {
        #pragma unroll
        for (int e = 0; e < NE; e++) atomicAdd(&logits[e], p[e]);
    }
    __syncthreads();
    if (tid == 0) {
        float v0 = -1e30f, v1 = -1e30f; int i0 = 0, i1 = 0;
        for (int e = 0; e < NE; e++) {
            float v = logits[e];
            if (v > v0) { v1 = v0; i1 = i0; v0 = v; i0 = e; }
            else if (v > v1) { v1 = v; i1 = e; }
        }
        float e1 = __expf(v1 - v0);
        float g0 = 1.f / (1.f + e1);
        g_te[n * 2 + 0] = i0; g_te[n * 2 + 1] = i1;
        g_tg[n * 2 + 0] = g0; g_tg[n * 2 + 1] = 1.f - g0;
    }
}

// ---------------- main kernel: one CTA (256 thr) per (node, slot) ----------------
__global__ __launch_bounds__(256, 2) void moe_kernel(
    const float* __restrict__ node_features,
    const float* __restrict__ edge_features,
    const float* __restrict__ edge_raw,
    const int*   __restrict__ neighbor_list,
    const float* __restrict__ neighbor_mask,
    const float* __restrict__ attn_mask,
    const float* __restrict__ b_edge, const float* __restrict__ b_node,
    const float* __restrict__ b_msg,  const float* __restrict__ b_qkv,
    const float* __restrict__ b_out,
    const float* __restrict__ lag_, const float* __restrict__ lab_,
    const float* __restrict__ lfg_, const float* __restrict__ lfb_,
    const float* __restrict__ b1n, const float* __restrict__ b2n,
    const float* __restrict__ b1e, const float* __restrict__ b2e,
    float* __restrict__ out)
{
    extern __shared__ float sm[];
    float* sA   = sm;                 // KK*SS
    float* sB   = sA + KK * SS;
    float* sC   = sB + KK * SS;
    float* sNh  = sC + KK * SS;       // HH
    float* sVec = sNh + HH;           // HH
    float* sHn  = sVec + HH;          // FF
    float* sMsk = sHn + FF;           // KK
    float* sAm  = sMsk + KK;          // KK
    float* sRed = sAm + KK;           // 8

    const int n = blockIdx.x;
    const int slot = blockIdx.y;
    const int tid = threadIdx.x;
    const int lane = tid & 31, wid = tid >> 5;
    const int j = tid;
    const int cq = (tid & 63) * 4;     // 4 adjacent output cols
    const int rbase = (tid >> 6) * 8;  // 8 rows

    const int e = g_te[n * 2 + slot];
    const float gate = g_tg[n * 2 + slot];
    const float* lag = lag_ + e * HH;
    const float* lab = lab_ + e * HH;
    const float* lfg = lfg_ + e * HH;
    const float* lfb = lfb_ + e * HH;

    if (tid < KK) {
        sMsk[tid] = neighbor_mask[n * KK + tid];
        sAm[tid]  = attn_mask[n * KK + tid];
    }
    __syncthreads();
    float cnt = 0.f;
    #pragma unroll
    for (int k = 0; k < KK; k++) cnt += sMsk[k];
    float inv_cnt = 1.f / (cnt + 1e-5f);

    const float xj = node_features[(size_t)n * HH + j];

    // ---- recv layernorm -> sNh ----
    {
        float s = bsum256(xj, sRed);
        float mu = s * (1.f / HH);
        float d = xj - mu;
        float q = bsum256(d * d, sRed);
        float rs = rsqrtf(q * (1.f / HH) + 1e-5f);
        sNh[j] = d * rs * lag[j] + lab[j];
    }
    __syncthreads();

    // ---- edge_raw -> sA (32x128 dense) ----
    {
        const float4* src = (const float4*)(edge_raw + (size_t)n * KK * DEn);
        float4* dst = (float4*)sA;
        #pragma unroll
        for (int i = 0; i < 4; i++) dst[tid + 256 * i] = src[tid + 256 * i];
    }
    // ---- rv = recv @ Wn_bottom + bn -> sVec ----
    {
        const ull* W = g_wp + OFF_WN + (size_t)e * 65536u + 128u * 256u + j;
        ull a0 = pk2(b_node[e * HH + j], 0.f);
        ull a1 = pk2(0.f, 0.f), a2 = pk2(0.f, 0.f), a3 = pk2(0.f, 0.f);
        #pragma unroll 8
        for (int i = 0; i < 128; i += 4) {
            fma2(a0, *(const ull*)(sNh + 2 * i),     W[(size_t)i * 256]);
            fma2(a1, *(const ull*)(sNh + 2 * i + 2), W[(size_t)(i + 1) * 256]);
            fma2(a2, *(const ull*)(sNh + 2 * i + 4), W[(size_t)(i + 2) * 256]);
            fma2(a3, *(const ull*)(sNh + 2 * i + 6), W[(size_t)(i + 3) * 256]);
        }
        sVec[j] = fold(a0) + fold(a1) + fold(a2) + fold(a3);
    }
    __syncthreads();

    // ---- eh = gelu(edge_raw(sA) @ We + be) -> sB ----
    {
        ull acc[8][4];
        initacc(acc, b_edge + e * HH, cq);
        gemm8x4(acc, sA, DEn, DEn, g_wp + OFF_WE + (size_t)e * 16384u, 256, cq, rbase);
        storeacc(acc, sB, SS, cq, rbase, true);
    }
    __syncthreads();

    // ---- sender = LN(node_features[nbr]) -> sA ----
    for (int k = wid; k < KK; k += 8) {
        int nbr = neighbor_list[n * KK + k];
        const float* x = node_features + (size_t)nbr * HH;
        float v[8]; float s = 0.f;
        #pragma unroll
        for (int i = 0; i < 8; i++) { v[i] = x[lane + 32 * i]; s += v[i]; }
        #pragma unroll
        for (int o = 16; o; o >>= 1) s += __shfl_xor_sync(0xffffffffu, s, o);
        float mu = s * (1.f / HH);
        float q = 0.f;
        #pragma unroll
        for (int i = 0; i < 8; i++) { float d = v[i] - mu; q += d * d; }
        #pragma unroll
        for (int o = 16; o; o >>= 1) q += __shfl_xor_sync(0xffffffffu, q, o);
        float rs = rsqrtf(q * (1.f / HH) + 1e-5f);
        #pragma unroll
        for (int i = 0; i < 8; i++) {
            int cc = lane + 32 * i;
            sA[k * SS + cc] = (v[i] - mu) * rs * lag[cc] + lab[cc];
        }
    }
    __syncthreads();

    // ---- nodeh = gelu(sender(sA)@Wn_top + rv) -> sC ----
    {
        ull acc[8][4];
        initacc(acc, sVec, cq);
        gemm8x4(acc, sA, SS, HH, g_wp + OFF_WN + (size_t)e * 65536u, 256, cq, rbase);
        storeacc(acc, sC, SS, cq, rbase, true);
    }
    __syncthreads();

    // ---- msg = gelu(eh(sB)@Wm_top + nodeh(sC)@Wm_bot + bm) -> sA ----
    {
        const ull* Wt = g_wp + OFF_WM + (size_t)e * 65536u;
        ull acc[8][4];
        initacc(acc, b_msg + e * HH, cq);
        gemm8x4(acc, sB, SS, HH, Wt, 256, cq, rbase);
        gemm8x4(acc, sC, SS, HH, Wt + 128u * 256u, 256, cq, rbase);
        storeacc(acc, sA, SS, cq, rbase, true);
    }
    __syncthreads();

    // ---- qkv from msg(sA): q->sB, k->sC, v->sA (in-place after barrier) ----
    {
        const ull* W = g_wp + OFF_WQKV + (size_t)e * 98304u;
        const float* bq = b_qkv + e * 3 * HH;
        {
            ull acc[8][4];
            initacc(acc, bq, cq);
            gemm8x4(acc, sA, SS, HH, W, 768, cq, rbase);
            storeacc(acc, sB, SS, cq, rbase, false);
        }
        {
            ull acc[8][4];
            initacc(acc, bq + 256, cq);
            gemm8x4(acc, sA, SS, HH, W + 256, 768, cq, rbase);
            storeacc(acc, sC, SS, cq, rbase, false);
        }
        {
            ull acc[8][4];
            initacc(acc, bq + 512, cq);
            gemm8x4(acc, sA, SS, HH, W + 512, 768, cq, rbase);
            __syncthreads();                  // all reads of msg complete
            storeacc(acc, sA, SS, cq, rbase, false);
        }
    }
    __syncthreads();

    // ---- attention: warp = head, lane = query. q(sB), k(sC), v(sA) -> sB ----
    {
        int h = wid;
        int a = lane;
        float qv[DHn];
        #pragma unroll
        for (int d = 0; d < DHn; d++) qv[d] = sB[a * SS + h * DHn + d];
        float sc[KK];
        const float scale = 0.17677669529663687f;   // 1/sqrt(32)
        #pragma unroll
        for (int b = 0; b < KK; b++) {
            float s = 0.f;
            #pragma unroll
            for (int d = 0; d < DHn; d++) s = fmaf(qv[d], sC[b * SS + h * DHn + d], s);
            sc[b] = s * scale + sAm[b];
        }
        float m = sc[0];
        #pragma unroll
        for (int b = 1; b < KK; b++) m = fmaxf(m, sc[b]);
        float ssum = 0.f;
        #pragma unroll
        for (int b = 0; b < KK; b++) { sc[b] = __expf(sc[b] - m); ssum += sc[b]; }
        float inv = 1.f / ssum;
        float o[DHn];
        #pragma unroll
        for (int d = 0; d < DHn; d++) o[d] = 0.f;
        #pragma unroll
        for (int b = 0; b < KK; b++) {
            float p = sc[b] * inv;
            #pragma unroll
            for (int d = 0; d < DHn; d++) o[d] = fmaf(p, sA[b * SS + h * DHn + d], o[d]);
        }
        #pragma unroll
        for (int d = 0; d < DHn; d++) sB[a * SS + h * DHn + d] = o[d];
    }
    __syncthreads();

    // ---- edge_out = attn_out(sB) @ Wo + bo -> sC ----
    {
        ull acc[8][4];
        initacc(acc, b_out + e * HH, cq);
        gemm8x4(acc, sB, SS, HH, g_wp + OFF_WO + (size_t)e * 32768u, 256, cq, rbase);
        storeacc(acc, sC, SS, cq, rbase, false);
    }
    __syncthreads();

    // ---- masked-mean aggregate -> nfj ----
    float nfj;
    {
        float s = 0.f;
        #pragma unroll
        for (int k = 0; k < KK; k++) s += sC[k * SS + j] * sMsk[k];
        nfj = s * inv_cnt + xj;
    }
    __syncthreads();
    // ---- ef = edge_out + edge_features (RMW sC) ----
    {
        const float4* efsrc = (const float4*)(edge_features + (size_t)n * KK * HH);
        #pragma unroll
        for (int i = 0; i < 8; i++) {
            int idx = tid + 256 * i;           // float4 idx, 64 per row
            int row = idx >> 6, c4 = (idx & 63) * 4;
            float4* d4 = (float4*)(sC + row * SS + c4);
            float4 v = *d4;
            float4 a = efsrc[idx];
            v.x += a.x; v.y += a.y; v.z += a.z; v.w += a.w;
            *d4 = v;
        }
    }
    __syncthreads();

    // ---- node FFN LN -> sVec ----
    {
        float s = bsum256(nfj, sRed);
        float mu = s * (1.f / HH);
        float d = nfj - mu;
        float q = bsum256(d * d, sRed);
        float rs = rsqrtf(q * (1.f / HH) + 1e-5f);
        sVec[j] = d * rs * lfg[j] + lfb[j];
    }
    __syncthreads();
    // ---- W1n: 2 outputs per thread ----
    {
        const ull* W = g_wp + OFF_W1N + (size_t)e * 65536u;
        ull a0 = pk2(b1n[e * FF + tid], 0.f), a1 = pk2(0.f, 0.f);
        ull c0 = pk2(b1n[e * FF + tid + 256], 0.f), c1 = pk2(0.f, 0.f);
        #pragma unroll 8
        for (int i = 0; i < 128; i += 2) {
            ull x0 = *(const ull*)(sVec + 2 * i);
            ull x1 = *(const ull*)(sVec + 2 * i + 2);
            fma2(a0, x0, W[(size_t)i * 512 + tid]);
            fma2(c0, x0, W[(size_t)i * 512 + tid + 256]);
            fma2(a1, x1, W[(size_t)(i + 1) * 512 + tid]);
            fma2(c1, x1, W[(size_t)(i + 1) * 512 + tid + 256]);
        }
        sHn[tid]       = gelu_f(fold(a0) + fold(a1));
        sHn[tid + 256] = gelu_f(fold(c0) + fold(c1));
    }
    __syncthreads();
    // ---- W2n -> node_final ----
    float node_final;
    {
        const ull* W = g_wp + OFF_W2N + (size_t)e * 65536u + j;
        ull a0 = pk2(b2n[e * HH + j], 0.f);
        ull a1 = pk2(0.f, 0.f), a2 = pk2(0.f, 0.f), a3 = pk2(0.f, 0.f);
        #pragma unroll 8
        for (int i = 0; i < 256; i += 4) {
            fma2(a0, *(const ull*)(sHn + 2 * i),     W[(size_t)i * 256]);
            fma2(a1, *(const ull*)(sHn + 2 * i + 2), W[(size_t)(i + 1) * 256]);
            fma2(a2, *(const ull*)(sHn + 2 * i + 4), W[(size_t)(i + 2) * 256]);
            fma2(a3, *(const ull*)(sHn + 2 * i + 6), W[(size_t)(i + 3) * 256]);
        }
        node_final = nfj + fold(a0) + fold(a1) + fold(a2) + fold(a3);
    }

    // ---- edge FFN: eh2 = LN(ef(sC)) -> sA ----
    for (int k = wid; k < KK; k += 8) {
        float v[8]; float s = 0.f;
        #pragma unroll
        for (int i = 0; i < 8; i++) { v[i] = sC[k * SS + lane + 32 * i]; s += v[i]; }
        #pragma unroll
        for (int o = 16; o; o >>= 1) s += __shfl_xor_sync(0xffffffffu, s, o);
        float mu = s * (1.f / HH);
        float q = 0.f;
        #pragma unroll
        for (int i = 0; i < 8; i++) { float d = v[i] - mu; q += d * d; }
        #pragma unroll
        for (int o = 16; o; o >>= 1) q += __shfl_xor_sync(0xffffffffu, q, o);
        float rs = rsqrtf(q * (1.f / HH) + 1e-5f);
        #pragma unroll
        for (int i = 0; i < 8; i++) {
            int cc = lane + 32 * i;
            sA[k * SS + cc] = (v[i] - mu) * rs * lfg[cc] + lfb[cc];
        }
    }
    __syncthreads();

    // ---- hidden0 = gelu(eh2(sA)@W1e[:, :256]) -> sB ----
    {
        ull acc[8][4];
        initacc(acc, b1e + e * FF, cq);
        gemm8x4(acc, sA, SS, HH, g_wp + OFF_W1E + (size_t)e * 65536u, 512, cq, rbase);
        storeacc(acc, sB, SS, cq, rbase, true);
    }
    __syncthreads();
    // ---- sC += b2e + hidden0(sB) @ W2e_top ----
    {
        ull acc[8][4];
        initacc(acc, b2e + e * HH, cq);
        gemm8x4(acc, sB, SS, HH, g_wp + OFF_W2E + (size_t)e * 65536u, 256, cq, rbase);
        #pragma unroll
        for (int r = 0; r < 8; r++) {
            float4* d4 = (float4*)(sC + (rbase + r) * SS + cq);
            float4 v = *d4;
            v.x += fold(acc[r][0]); v.y += fold(acc[r][1]);
            v.z += fold(acc[r][2]); v.w += fold(acc[r][3]);
            *d4 = v;
        }
    }
    __syncthreads();
    // ---- hidden1 = gelu(eh2(sA)@W1e[:, 256:]) -> sB ----
    {
        ull acc[8][4];
        initacc(acc, b1e + e * FF + 256, cq);
        gemm8x4(acc, sA, SS, HH, g_wp + OFF_W1E + (size_t)e * 65536u + 256, 512, cq, rbase);
        storeacc(acc, sB, SS, cq, rbase, true);
    }
    __syncthreads();
    // ---- final = sC + hidden1(sB)@W2e_bot ; atomic write ----
    {
        ull acc[8][4];
        #pragma unroll
        for (int r = 0; r < 8; r++)
            #pragma unroll
            for (int t = 0; t < 4; t++) acc[r][t] = pk2(0.f, 0.f);
        gemm8x4(acc, sB, SS, HH, g_wp + OFF_W2E + (size_t)e * 65536u + 128u * 256u,
                256, cq, rbase);
        float* eout = out + (size_t)NN * HH + (size_t)n * KK * HH;
        #pragma unroll
        for (int r = 0; r < 8; r++) {
            int row = rbase + r;
            const float* c = sC + row * SS + cq;
            float* o = eout + (size_t)row * HH + cq;
            atomicAdd(o + 0, gate * (c[0] + fold(acc[r][0])));
            atomicAdd(o + 1, gate * (c[1] + fold(acc[r][1])));
            atomicAdd(o + 2, gate * (c[2] + fold(acc[r][2])));
            atomicAdd(o + 3, gate * (c[3] + fold(acc[r][3])));
        }
    }
    atomicAdd(out + (size_t)n * HH + j, gate * node_final);
}

static constexpr int SMEM_FLOATS = 3 * KK * SS + HH + HH + FF + KK + KK + 8;
static constexpr int SMEM_BYTES  = SMEM_FLOATS * 4;

extern "C" void kernel_launch(void* const* d_in, const int* in_sizes, int n_in,
                              void* d_out, int out_size) {
    const float* node_features = (const float*)d_in[0];
    const float* edge_features = (const float*)d_in[1];
    const float* edge_raw      = (const float*)d_in[2];
    const int*   neighbor_list = (const int*)  d_in[3];
    const float* neighbor_mask = (const float*)d_in[4];
    const float* attn_mask     = (const float*)d_in[5];
    const float* w_gate        = (const float*)d_in[6];
    const float* W_edge = (const float*)d_in[7];
    const float* b_edge = (const float*)d_in[8];
    const float* W_node = (const float*)d_in[9];
    const float* b_node = (const float*)d_in[10];
    const float* W_msg  = (const float*)d_in[11];
    const float* b_msg  = (const float*)d_in[12];
    const float* W_qkv  = (const float*)d_in[13];
    const float* b_qkv  = (const float*)d_in[14];
    const float* W_out  = (const float*)d_in[15];
    const float* b_out  = (const float*)d_in[16];
    const float* lag    = (const float*)d_in[17];
    const float* lab    = (const float*)d_in[18];
    const float* lfg    = (const float*)d_in[19];
    const float* lfb    = (const float*)d_in[20];
    const float* W1n = (const float*)d_in[21];
    const float* b1n = (const float*)d_in[22];
    const float* W2n = (const float*)d_in[23];
    const float* b2n = (const float*)d_in[24];
    const float* W1e = (const float*)d_in[25];
    const float* b1e = (const float*)d_in[26];
    const float* W2e = (const float*)d_in[27];
    const float* b2e = (const float*)d_in[28];
    float* out = (float*)d_out;

    cudaFuncSetAttribute(moe_kernel, cudaFuncAttributeMaxDynamicSharedMemorySize, SMEM_BYTES);

    dim3 rg(128, 9);
    repack_all<<<rg, 256>>>(W_edge, W_node, W_msg, W_qkv, W_out, W1n, W2n, W1e, W2e);
    gate_kernel<<<NN, 256>>>(node_features, w_gate);
    zero_kernel<<<512, 256>>>((float4*)out, out_size / 4);

    dim3 grid(NN, 2);
    moe_kernel<<<grid, 256, SMEM_BYTES>>>(
        node_features, edge_features, edge_raw, neighbor_list, neighbor_mask,
        attn_mask, b_edge, b_node, b_msg, b_qkv, b_out,
        lag, lab, lfg, lfb, b1n, b2n, b1e, b2e, out);
}

// round 7
// speedup vs baseline: 1.2236x; 1.0708x over previous
#include <cuda_runtime.h>
#include <math.h>

#define NN 1024
#define KK 32
#define HH 256
#define DEn 128
#define NE 8
#define NHn 8
#define DHn 32
#define FF 512
#define SS 260   // 16B-aligned padded slot stride

typedef unsigned long long ull;

__device__ int   g_te[NN * 2];
__device__ float g_tg[NN * 2];

// prepacked weights: k-pairs (W[k][j], W[k+1][j]) in one ull
#define OFF_WE   0u
#define OFF_WN   131072u
#define OFF_WM   655360u
#define OFF_WQKV 1179648u
#define OFF_WO   1966080u
#define OFF_W1N  2228224u
#define OFF_W2N  2752512u
#define OFF_W1E  3276800u
#define OFF_W2E  3801088u
#define WP_TOTAL 4325376u
__device__ ull g_wp[WP_TOTAL];

__device__ __forceinline__ float gelu_f(float x) {
    float u = 0.7978845608028654f * (x + 0.044715f * x * x * x);
    float e = __expf(2.f * u);
    float t = 1.f - __fdividef(2.f, e + 1.f);
    return 0.5f * x * (1.f + t);
}
__device__ __forceinline__ ull pk2(float lo, float hi) {
    ull r; asm("mov.b64 %0,{%1,%2};" : "=l"(r) : "f"(lo), "f"(hi)); return r;
}
__device__ __forceinline__ void upk2(ull v, float& lo, float& hi) {
    asm("mov.b64 {%0,%1},%2;" : "=f"(lo), "=f"(hi) : "l"(v));
}
__device__ __forceinline__ void fma2(ull& d, ull a, ull b) {
    asm("fma.rn.f32x2 %0,%1,%2,%0;" : "+l"(d) : "l"(a), "l"(b));
}
__device__ __forceinline__ float fold(ull v) {
    float lo, hi; upk2(v, lo, hi); return lo + hi;
}

__device__ __forceinline__ float bsum256(float v, float* red) {
    #pragma unroll
    for (int o = 16; o; o >>= 1) v += __shfl_xor_sync(0xffffffffu, v, o);
    int tid = threadIdx.x;
    if ((tid & 31) == 0) red[tid >> 5] = v;
    __syncthreads();
    float s = red[0] + red[1] + red[2] + red[3] + red[4] + red[5] + red[6] + red[7];
    __syncthreads();
    return s;
}

// ---- 8-row x 4-col f32x2 GEMM: batched loads, pointer-bump addressing ----
__device__ __forceinline__ void initacc(ull acc[8][4], const float* bias, int cq) {
    float4 b = *(const float4*)(bias + cq);
    ull b0 = pk2(b.x, 0.f), b1 = pk2(b.y, 0.f), b2 = pk2(b.z, 0.f), b3 = pk2(b.w, 0.f);
    #pragma unroll
    for (int r = 0; r < 8; r++) {
        acc[r][0] = b0; acc[r][1] = b1; acc[r][2] = b2; acc[r][3] = b3;
    }
}

__device__ __forceinline__ void gemm8x4(ull acc[8][4],
    const float* __restrict__ sIn, const int inS, const int hin,
    const ull* __restrict__ Wp, const int wld, int cq, int rbase)
{
    const float* ip = sIn + rbase * inS;
    const ull* w = Wp + cq;
    #pragma unroll 2
    for (int k = 0; k < hin; k += 4) {
        ulonglong2 wa0 = *(const ulonglong2*)w;
        ulonglong2 wa1 = *(const ulonglong2*)(w + 2);
        ulonglong2 wb0 = *(const ulonglong2*)(w + wld);
        ulonglong2 wb1 = *(const ulonglong2*)(w + wld + 2);
        ulonglong2 x[8];
        #pragma unroll
        for (int r = 0; r < 8; r++) x[r] = *(const ulonglong2*)(ip + r * inS);
        w += 2 * wld;
        ip += 4;
        #pragma unroll
        for (int r = 0; r < 8; r++) {
            fma2(acc[r][0], x[r].x, wa0.x); fma2(acc[r][1], x[r].x, wa0.y);
            fma2(acc[r][2], x[r].x, wa1.x); fma2(acc[r][3], x[r].x, wa1.y);
            fma2(acc[r][0], x[r].y, wb0.x); fma2(acc[r][1], x[r].y, wb0.y);
            fma2(acc[r][2], x[r].y, wb1.x); fma2(acc[r][3], x[r].y, wb1.y);
        }
    }
}

__device__ __forceinline__ void storeacc(const ull acc[8][4], float* sOut,
                                         int outS, int cq, int rbase, bool g) {
    #pragma unroll
    for (int r = 0; r < 8; r++) {
        float4 v;
        v.x = fold(acc[r][0]); v.y = fold(acc[r][1]);
        v.z = fold(acc[r][2]); v.w = fold(acc[r][3]);
        if (g) { v.x = gelu_f(v.x); v.y = gelu_f(v.y); v.z = gelu_f(v.z); v.w = gelu_f(v.w); }
        *(float4*)(sOut + (rbase + r) * outS + cq) = v;
    }
}

// ---- warp LayerNorm over 256 contiguous floats; lane owns cols lane*8..+7 ----
__device__ __forceinline__ void warp_ln(const float* __restrict__ src4,  // 16B-aligned
                                        float* __restrict__ dst,
                                        const float* __restrict__ gam,
                                        const float* __restrict__ bet, int lane) {
    float4 v0 = *(const float4*)(src4 + lane * 8);
    float4 v1 = *(const float4*)(src4 + lane * 8 + 4);
    float s = v0.x + v0.y + v0.z + v0.w + v1.x + v1.y + v1.z + v1.w;
    #pragma unroll
    for (int o = 16; o; o >>= 1) s += __shfl_xor_sync(0xffffffffu, s, o);
    float mu = s * (1.f / HH);
    float q =
        (v0.x - mu) * (v0.x - mu) + (v0.y - mu) * (v0.y - mu) +
        (v0.z - mu) * (v0.z - mu) + (v0.w - mu) * (v0.w - mu) +
        (v1.x - mu) * (v1.x - mu) + (v1.y - mu) * (v1.y - mu) +
        (v1.z - mu) * (v1.z - mu) + (v1.w - mu) * (v1.w - mu);
    #pragma unroll
    for (int o = 16; o; o >>= 1) q += __shfl_xor_sync(0xffffffffu, q, o);
    float rs = rsqrtf(q * (1.f / HH) + 1e-5f);
    float4 g0 = *(const float4*)(gam + lane * 8);
    float4 g1 = *(const float4*)(gam + lane * 8 + 4);
    float4 b0 = *(const float4*)(bet + lane * 8);
    float4 b1 = *(const float4*)(bet + lane * 8 + 4);
    float4 o0, o1;
    o0.x = (v0.x - mu) * rs * g0.x + b0.x;
    o0.y = (v0.y - mu) * rs * g0.y + b0.y;
    o0.z = (v0.z - mu) * rs * g0.z + b0.z;
    o0.w = (v0.w - mu) * rs * g0.w + b0.w;
    o1.x = (v1.x - mu) * rs * g1.x + b1.x;
    o1.y = (v1.y - mu) * rs * g1.y + b1.y;
    o1.z = (v1.z - mu) * rs * g1.z + b1.z;
    o1.w = (v1.w - mu) * rs * g1.w + b1.w;
    *(float4*)(dst + lane * 8) = o0;
    *(float4*)(dst + lane * 8 + 4) = o1;
}

// ---------------- fused weight repack ----------------
__device__ __forceinline__ void rp_seg(const float* __restrict__ src,
                                       ull* __restrict__ dst, int rows2, int cols) {
    int idx = blockIdx.x * blockDim.x + threadIdx.x;
    int total = rows2 * cols;
    int stride = gridDim.x * blockDim.x;
    for (; idx < total; idx += stride) {
        int r2 = idx / cols, cc = idx - r2 * cols;
        dst[idx] = pk2(src[(size_t)(2 * r2) * cols + cc],
                       src[(size_t)(2 * r2 + 1) * cols + cc]);
    }
}

__global__ void repack_all(
    const float* We, const float* Wn, const float* Wm, const float* Wq,
    const float* Wo, const float* w1n, const float* w2n,
    const float* w1e, const float* w2e)
{
    switch (blockIdx.y) {
        case 0: rp_seg(We,  g_wp + OFF_WE,   512, 256); break;
        case 1: rp_seg(Wn,  g_wp + OFF_WN,  2048, 256); break;
        case 2: rp_seg(Wm,  g_wp + OFF_WM,  2048, 256); break;
        case 3: rp_seg(Wq,  g_wp + OFF_WQKV,1024, 768); break;
        case 4: rp_seg(Wo,  g_wp + OFF_WO,  1024, 256); break;
        case 5: rp_seg(w1n, g_wp + OFF_W1N, 1024, 512); break;
        case 6: rp_seg(w2n, g_wp + OFF_W2N, 2048, 256); break;
        case 7: rp_seg(w1e, g_wp + OFF_W1E, 1024, 512); break;
        case 8: rp_seg(w2e, g_wp + OFF_W2E, 2048, 256); break;
    }
}

// ---------------- zero output ----------------
__global__ void zero_kernel(float4* __restrict__ p, int n4) {
    int idx = blockIdx.x * blockDim.x + threadIdx.x;
    int stride = gridDim.x * blockDim.x;
    float4 z = make_float4(0.f, 0.f, 0.f, 0.f);
    for (; idx < n4; idx += stride) p[idx] = z;
}

// ---------------- gating kernel ----------------
__global__ void gate_kernel(const float* __restrict__ nf, const float* __restrict__ wg) {
    int n = blockIdx.x;
    int tid = threadIdx.x;
    float x = nf[n * HH + tid];
    float p[NE];
    #pragma unroll
    for (int e = 0; e < NE; e++) p[e] = x * wg[tid * NE + e];
    #pragma unroll
    for (int e = 0; e < NE; e++)
        #pragma unroll
        for (int o = 16; o; o >>= 1) p[e] += __shfl_xor_sync(0xffffffffu, p[e], o);
    __shared__ float logits[NE];
    if (tid < NE) logits[tid] = 0.f;
    __syncthreads();
    if ((tid & 31) == 0) {
        #pragma unroll
        for (int e = 0; e < NE; e++) atomicAdd(&logits[e], p[e]);
    }
    __syncthreads();
    if (tid == 0) {
        float v0 = -1e30f, v1 = -1e30f; int i0 = 0, i1 = 0;
        for (int e = 0; e < NE; e++) {
            float v = logits[e];
            if (v > v0) { v1 = v0; i1 = i0; v0 = v; i0 = e; }
            else if (v > v1) { v1 = v; i1 = e; }
        }
        float e1 = __expf(v1 - v0);
        float g0 = 1.f / (1.f + e1);
        g_te[n * 2 + 0] = i0; g_te[n * 2 + 1] = i1;
        g_tg[n * 2 + 0] = g0; g_tg[n * 2 + 1] = 1.f - g0;
    }
}

// ---------------- main kernel: one CTA (256 thr) per (node, slot) ----------------
__global__ __launch_bounds__(256, 2) void moe_kernel(
    const float* __restrict__ node_features,
    const float* __restrict__ edge_features,
    const float* __restrict__ edge_raw,
    const int*   __restrict__ neighbor_list,
    const float* __restrict__ neighbor_mask,
    const float* __restrict__ attn_mask,
    const float* __restrict__ b_edge, const float* __restrict__ b_node,
    const float* __restrict__ b_msg,  const float* __restrict__ b_qkv,
    const float* __restrict__ b_out,
    const float* __restrict__ lag_, const float* __restrict__ lab_,
    const float* __restrict__ lfg_, const float* __restrict__ lfb_,
    const float* __restrict__ b1n, const float* __restrict__ b2n,
    const float* __restrict__ b1e, const float* __restrict__ b2e,
    float* __restrict__ out)
{
    extern __shared__ float sm[];
    float* sA   = sm;                 // KK*SS
    float* sB   = sA + KK * SS;
    float* sC   = sB + KK * SS;
    float* sNh  = sC + KK * SS;       // HH
    float* sVec = sNh + HH;           // HH
    float* sHn  = sVec + HH;          // FF
    float* sMsk = sHn + FF;           // KK
    float* sAm  = sMsk + KK;          // KK
    float* sRed = sAm + KK;           // 8

    const int n = blockIdx.x;
    const int slot = blockIdx.y;
    const int tid = threadIdx.x;
    const int lane = tid & 31, wid = tid >> 5;
    const int j = tid;
    const int cq = (tid & 63) * 4;     // 4 adjacent output cols
    const int rbase = (tid >> 6) * 8;  // 8 rows

    const int e = g_te[n * 2 + slot];
    const float gate = g_tg[n * 2 + slot];
    const float* lag = lag_ + e * HH;
    const float* lab = lab_ + e * HH;
    const float* lfg = lfg_ + e * HH;
    const float* lfb = lfb_ + e * HH;

    if (tid < KK) {
        sMsk[tid] = neighbor_mask[n * KK + tid];
        sAm[tid]  = attn_mask[n * KK + tid];
    }
    __syncthreads();
    float cnt = 0.f;
    #pragma unroll
    for (int k = 0; k < KK; k++) cnt += sMsk[k];
    float inv_cnt = 1.f / (cnt + 1e-5f);

    const float xj = node_features[(size_t)n * HH + j];

    // ---- recv layernorm -> sNh ----
    {
        float s = bsum256(xj, sRed);
        float mu = s * (1.f / HH);
        float d = xj - mu;
        float q = bsum256(d * d, sRed);
        float rs = rsqrtf(q * (1.f / HH) + 1e-5f);
        sNh[j] = d * rs * lag[j] + lab[j];
    }
    __syncthreads();

    // ---- edge_raw -> sA (32x128 dense) ----
    {
        const float4* src = (const float4*)(edge_raw + (size_t)n * KK * DEn);
        float4* dst = (float4*)sA;
        #pragma unroll
        for (int i = 0; i < 4; i++) dst[tid + 256 * i] = src[tid + 256 * i];
    }
    // ---- rv = recv @ Wn_bottom + bn -> sVec ----
    {
        const ull* W = g_wp + OFF_WN + (size_t)e * 65536u + 128u * 256u + j;
        ull a0 = pk2(b_node[e * HH + j], 0.f);
        ull a1 = pk2(0.f, 0.f), a2 = pk2(0.f, 0.f), a3 = pk2(0.f, 0.f);
        #pragma unroll 8
        for (int i = 0; i < 128; i += 4) {
            fma2(a0, *(const ull*)(sNh + 2 * i),     W[(size_t)i * 256]);
            fma2(a1, *(const ull*)(sNh + 2 * i + 2), W[(size_t)(i + 1) * 256]);
            fma2(a2, *(const ull*)(sNh + 2 * i + 4), W[(size_t)(i + 2) * 256]);
            fma2(a3, *(const ull*)(sNh + 2 * i + 6), W[(size_t)(i + 3) * 256]);
        }
        sVec[j] = fold(a0) + fold(a1) + fold(a2) + fold(a3);
    }
    __syncthreads();

    // ---- eh = gelu(edge_raw(sA) @ We + be) -> sB ----
    {
        ull acc[8][4];
        initacc(acc, b_edge + e * HH, cq);
        gemm8x4(acc, sA, DEn, DEn, g_wp + OFF_WE + (size_t)e * 16384u, 256, cq, rbase);
        storeacc(acc, sB, SS, cq, rbase, true);
    }
    __syncthreads();

    // ---- sender = LN(node_features[nbr]) -> sA (warp per row) ----
    for (int k = wid; k < KK; k += 8) {
        int nbr = neighbor_list[n * KK + k];
        warp_ln(node_features + (size_t)nbr * HH, sA + k * SS, lag, lab, lane);
    }
    __syncthreads();

    // ---- nodeh = gelu(sender(sA)@Wn_top + rv) -> sC ----
    {
        ull acc[8][4];
        initacc(acc, sVec, cq);
        gemm8x4(acc, sA, SS, HH, g_wp + OFF_WN + (size_t)e * 65536u, 256, cq, rbase);
        storeacc(acc, sC, SS, cq, rbase, true);
    }
    __syncthreads();

    // ---- msg = gelu(eh(sB)@Wm_top + nodeh(sC)@Wm_bot + bm) -> sA ----
    {
        const ull* Wt = g_wp + OFF_WM + (size_t)e * 65536u;
        ull acc[8][4];
        initacc(acc, b_msg + e * HH, cq);
        gemm8x4(acc, sB, SS, HH, Wt, 256, cq, rbase);
        gemm8x4(acc, sC, SS, HH, Wt + 128u * 256u, 256, cq, rbase);
        storeacc(acc, sA, SS, cq, rbase, true);
    }
    __syncthreads();

    // ---- qkv from msg(sA): q->sB, k->sC, v->sA (in-place after barrier) ----
    {
        const ull* W = g_wp + OFF_WQKV + (size_t)e * 98304u;
        const float* bq = b_qkv + e * 3 * HH;
        {
            ull acc[8][4];
            initacc(acc, bq, cq);
            gemm8x4(acc, sA, SS, HH, W, 768, cq, rbase);
            storeacc(acc, sB, SS, cq, rbase, false);
        }
        {
            ull acc[8][4];
            initacc(acc, bq + 256, cq);
            gemm8x4(acc, sA, SS, HH, W + 256, 768, cq, rbase);
            storeacc(acc, sC, SS, cq, rbase, false);
        }
        {
            ull acc[8][4];
            initacc(acc, bq + 512, cq);
            gemm8x4(acc, sA, SS, HH, W + 512, 768, cq, rbase);
            __syncthreads();                  // all reads of msg complete
            storeacc(acc, sA, SS, cq, rbase, false);
        }
    }
    __syncthreads();

    // ---- attention (f32x2): warp = head, lane = query. q(sB), k(sC), v(sA) -> sB ----
    {
        const int h = wid;
        const int a = lane;
        const float* qp = sB + a * SS + h * DHn;
        ulonglong2 qv[8];
        #pragma unroll
        for (int i = 0; i < 8; i++) qv[i] = *(const ulonglong2*)(qp + 4 * i);
        float sc[KK];
        const float scale = 0.17677669529663687f;   // 1/sqrt(32)
        #pragma unroll
        for (int b = 0; b < KK; b++) {
            const float* kp = sC + b * SS + h * DHn;
            ull d0 = pk2(0.f, 0.f), d1 = pk2(0.f, 0.f);
            #pragma unroll
            for (int i = 0; i < 8; i++) {
                ulonglong2 kv = *(const ulonglong2*)(kp + 4 * i);
                fma2(d0, qv[i].x, kv.x);
                fma2(d1, qv[i].y, kv.y);
            }
            sc[b] = (fold(d0) + fold(d1)) * scale + sAm[b];
        }
        float m = sc[0];
        #pragma unroll
        for (int b = 1; b < KK; b++) m = fmaxf(m, sc[b]);
        float ssum = 0.f;
        #pragma unroll
        for (int b = 0; b < KK; b++) { sc[b] = __expf(sc[b] - m); ssum += sc[b]; }
        float inv = 1.f / ssum;
        ull o[16];
        #pragma unroll
        for (int i = 0; i < 16; i++) o[i] = pk2(0.f, 0.f);
        #pragma unroll
        for (int b = 0; b < KK; b++) {
            float p = sc[b] * inv;
            ull pp = pk2(p, p);
            const float* vp = sA + b * SS + h * DHn;
            #pragma unroll
            for (int i = 0; i < 8; i++) {
                ulonglong2 vv = *(const ulonglong2*)(vp + 4 * i);
                fma2(o[2 * i], pp, vv.x);
                fma2(o[2 * i + 1], pp, vv.y);
            }
        }
        __syncthreads();                      // done reading q before overwrite
        float* op = sB + a * SS + h * DHn;
        #pragma unroll
        for (int i = 0; i < 16; i++) *(ull*)(op + 2 * i) = o[i];
    }
    __syncthreads();

    // ---- edge_out = attn_out(sB) @ Wo + bo -> sC ----
    {
        ull acc[8][4];
        initacc(acc, b_out + e * HH, cq);
        gemm8x4(acc, sB, SS, HH, g_wp + OFF_WO + (size_t)e * 32768u, 256, cq, rbase);
        storeacc(acc, sC, SS, cq, rbase, false);
    }
    __syncthreads();

    // ---- masked-mean aggregate -> nfj ----
    float nfj;
    {
        float s = 0.f;
        #pragma unroll
        for (int k = 0; k < KK; k++) s += sC[k * SS + j] * sMsk[k];
        nfj = s * inv_cnt + xj;
    }
    __syncthreads();
    // ---- ef = edge_out + edge_features (RMW sC) ----
    {
        const float4* efsrc = (const float4*)(edge_features + (size_t)n * KK * HH);
        #pragma unroll
        for (int i = 0; i < 8; i++) {
            int idx = tid + 256 * i;           // float4 idx, 64 per row
            int row = idx >> 6, c4 = (idx & 63) * 4;
            float4* d4 = (float4*)(sC + row * SS + c4);
            float4 v = *d4;
            float4 a = efsrc[idx];
            v.x += a.x; v.y += a.y; v.z += a.z; v.w += a.w;
            *d4 = v;
        }
    }
    __syncthreads();

    // ---- node FFN LN -> sVec ----
    {
        float s = bsum256(nfj, sRed);
        float mu = s * (1.f / HH);
        float d = nfj - mu;
        float q = bsum256(d * d, sRed);
        float rs = rsqrtf(q * (1.f / HH) + 1e-5f);
        sVec[j] = d * rs * lfg[j] + lfb[j];
    }
    __syncthreads();
    // ---- W1n: 2 outputs per thread ----
    {
        const ull* W = g_wp + OFF_W1N + (size_t)e * 65536u;
        ull a0 = pk2(b1n[e * FF + tid], 0.f), a1 = pk2(0.f, 0.f);
        ull c0 = pk2(b1n[e * FF + tid + 256], 0.f), c1 = pk2(0.f, 0.f);
        #pragma unroll 8
        for (int i = 0; i < 128; i += 2) {
            ull x0 = *(const ull*)(sVec + 2 * i);
            ull x1 = *(const ull*)(sVec + 2 * i + 2);
            fma2(a0, x0, W[(size_t)i * 512 + tid]);
            fma2(c0, x0, W[(size_t)i * 512 + tid + 256]);
            fma2(a1, x1, W[(size_t)(i + 1) * 512 + tid]);
            fma2(c1, x1, W[(size_t)(i + 1) * 512 + tid + 256]);
        }
        sHn[tid]       = gelu_f(fold(a0) + fold(a1));
        sHn[tid + 256] = gelu_f(fold(c0) + fold(c1));
    }
    __syncthreads();
    // ---- W2n -> node_final ----
    float node_final;
    {
        const ull* W = g_wp + OFF_W2N + (size_t)e * 65536u + j;
        ull a0 = pk2(b2n[e * HH + j], 0.f);
        ull a1 = pk2(0.f, 0.f), a2 = pk2(0.f, 0.f), a3 = pk2(0.f, 0.f);
        #pragma unroll 8
        for (int i = 0; i < 256; i += 4) {
            fma2(a0, *(const ull*)(sHn + 2 * i),     W[(size_t)i * 256]);
            fma2(a1, *(const ull*)(sHn + 2 * i + 2), W[(size_t)(i + 1) * 256]);
            fma2(a2, *(const ull*)(sHn + 2 * i + 4), W[(size_t)(i + 2) * 256]);
            fma2(a3, *(const ull*)(sHn + 2 * i + 6), W[(size_t)(i + 3) * 256]);
        }
        node_final = nfj + fold(a0) + fold(a1) + fold(a2) + fold(a3);
    }

    // ---- edge FFN: eh2 = LN(ef(sC)) -> sA (warp per row) ----
    for (int k = wid; k < KK; k += 8) {
        warp_ln(sC + k * SS, sA + k * SS, lfg, lfb, lane);
    }
    __syncthreads();

    // ---- hidden0 = gelu(eh2(sA)@W1e[:, :256]) -> sB ----
    {
        ull acc[8][4];
        initacc(acc, b1e + e * FF, cq);
        gemm8x4(acc, sA, SS, HH, g_wp + OFF_W1E + (size_t)e * 65536u, 512, cq, rbase);
        storeacc(acc, sB, SS, cq, rbase, true);
    }
    __syncthreads();
    // ---- sC += b2e + hidden0(sB) @ W2e_top ----
    {
        ull acc[8][4];
        initacc(acc, b2e + e * HH, cq);
        gemm8x4(acc, sB, SS, HH, g_wp + OFF_W2E + (size_t)e * 65536u, 256, cq, rbase);
        #pragma unroll
        for (int r = 0; r < 8; r++) {
            float4* d4 = (float4*)(sC + (rbase + r) * SS + cq);
            float4 v = *d4;
            v.x += fold(acc[r][0]); v.y += fold(acc[r][1]);
            v.z += fold(acc[r][2]); v.w += fold(acc[r][3]);
            *d4 = v;
        }
    }
    __syncthreads();
    // ---- hidden1 = gelu(eh2(sA)@W1e[:, 256:]) -> sB ----
    {
        ull acc[8][4];
        initacc(acc, b1e + e * FF + 256, cq);
        gemm8x4(acc, sA, SS, HH, g_wp + OFF_W1E + (size_t)e * 65536u + 256, 512, cq, rbase);
        storeacc(acc, sB, SS, cq, rbase, true);
    }
    __syncthreads();
    // ---- final = sC + hidden1(sB)@W2e_bot ; atomic write ----
    {
        ull acc[8][4];
        #pragma unroll
        for (int r = 0; r < 8; r++)
            #pragma unroll
            for (int t = 0; t < 4; t++) acc[r][t] = pk2(0.f, 0.f);
        gemm8x4(acc, sB, SS, HH, g_wp + OFF_W2E + (size_t)e * 65536u + 128u * 256u,
                256, cq, rbase);
        float* eout = out + (size_t)NN * HH + (size_t)n * KK * HH;
        #pragma unroll
        for (int r = 0; r < 8; r++) {
            int row = rbase + r;
            const float* c = sC + row * SS + cq;
            float* o = eout + (size_t)row * HH + cq;
            atomicAdd(o + 0, gate * (c[0] + fold(acc[r][0])));
            atomicAdd(o + 1, gate * (c[1] + fold(acc[r][1])));
            atomicAdd(o + 2, gate * (c[2] + fold(acc[r][2])));
            atomicAdd(o + 3, gate * (c[3] + fold(acc[r][3])));
        }
    }
    atomicAdd(out + (size_t)n * HH + j, gate * node_final);
}

static constexpr int SMEM_FLOATS = 3 * KK * SS + HH + HH + FF + KK + KK + 8;
static constexpr int SMEM_BYTES  = SMEM_FLOATS * 4;

extern "C" void kernel_launch(void* const* d_in, const int* in_sizes, int n_in,
                              void* d_out, int out_size) {
    const float* node_features = (const float*)d_in[0];
    const float* edge_features = (const float*)d_in[1];
    const float* edge_raw      = (const float*)d_in[2];
    const int*   neighbor_list = (const int*)  d_in[3];
    const float* neighbor_mask = (const float*)d_in[4];
    const float* attn_mask     = (const float*)d_in[5];
    const float* w_gate        = (const float*)d_in[6];
    const float* W_edge = (const float*)d_in[7];
    const float* b_edge = (const float*)d_in[8];
    const float* W_node = (const float*)d_in[9];
    const float* b_node = (const float*)d_in[10];
    const float* W_msg  = (const float*)d_in[11];
    const float* b_msg  = (const float*)d_in[12];
    const float* W_qkv  = (const float*)d_in[13];
    const float* b_qkv  = (const float*)d_in[14];
    const float* W_out  = (const float*)d_in[15];
    const float* b_out  = (const float*)d_in[16];
    const float* lag    = (const float*)d_in[17];
    const float* lab    = (const float*)d_in[18];
    const float* lfg    = (const float*)d_in[19];
    const float* lfb    = (const float*)d_in[20];
    const float* W1n = (const float*)d_in[21];
    const float* b1n = (const float*)d_in[22];
    const float* W2n = (const float*)d_in[23];
    const float* b2n = (const float*)d_in[24];
    const float* W1e = (const float*)d_in[25];
    const float* b1e = (const float*)d_in[26];
    const float* W2e = (const float*)d_in[27];
    const float* b2e = (const float*)d_in[28];
    float* out = (float*)d_out;

    cudaFuncSetAttribute(moe_kernel, cudaFuncAttributeMaxDynamicSharedMemorySize, SMEM_BYTES);

    dim3 rg(128, 9);
    repack_all<<<rg, 256>>>(W_edge, W_node, W_msg, W_qkv, W_out, W1n, W2n, W1e, W2e);
    gate_kernel<<<NN, 256>>>(node_features, w_gate);
    zero_kernel<<<512, 256>>>((float4*)out, out_size / 4);

    dim3 grid(NN, 2);
    moe_kernel<<<grid, 256, SMEM_BYTES>>>(
        node_features, edge_features, edge_raw, neighbor_list, neighbor_mask,
        attn_mask, b_edge, b_node, b_msg, b_qkv, b_out,
        lag, lab, lfg, lfb, b1n, b2n, b1e, b2e, out);
}